// round 1
// baseline (speedup 1.0000x reference)
#include <cuda_runtime.h>
#include <math.h>

#define Bb 8
#define Tt 2048
#define Cc 768
#define Hh 64
#define M_TOT (Bb*Tt)

// scratch for q, k, v projections (4 MB each)
__device__ float g_q[M_TOT*Hh];
__device__ float g_k[M_TOT*Hh];
__device__ float g_v[M_TOT*Hh];

// ---------------------------------------------------------------------------
// Kernel 1: QKV projection. X[16384,768] @ W[768,64] for each of Wq/Wk/Wv.
// BM=64, BN=64 (N=64 so one col-block per W), BK=16, 256 threads, 4x4/thread.
// grid = (256, 3): y selects which weight/output.
// ---------------------------------------------------------------------------
__global__ __launch_bounds__(256) void qkv_proj(
    const float* __restrict__ x,
    const float* __restrict__ Wq,
    const float* __restrict__ Wk,
    const float* __restrict__ Wv)
{
    __shared__ float Xs[16][68];   // Xs[k][m]  (transposed)
    __shared__ float Ws[16][68];   // Ws[k][n]

    const float* W  = (blockIdx.y == 0) ? Wq : (blockIdx.y == 1 ? Wk : Wv);
    float*       out= (blockIdx.y == 0) ? g_q : (blockIdx.y == 1 ? g_k : g_v);

    const int m0  = blockIdx.x * 64;
    const int tid = threadIdx.x;
    const int trow = (tid >> 4) << 2;   // 0..60
    const int tcol = (tid & 15) << 2;   // 0..60

    const int lxm = tid >> 2;           // X load: row 0..63
    const int lxk = (tid & 3) << 2;     // X load: k offset 0..12
    const int lwk = tid >> 4;           // W load: k 0..15
    const int lwn = (tid & 15) << 2;    // W load: n offset 0..60

    float acc[4][4];
#pragma unroll
    for (int i = 0; i < 4; i++)
#pragma unroll
        for (int j = 0; j < 4; j++) acc[i][j] = 0.f;

    for (int k0 = 0; k0 < Cc; k0 += 16) {
        float4 xa = *(const float4*)(x + (size_t)(m0 + lxm) * Cc + k0 + lxk);
        Xs[lxk + 0][lxm] = xa.x;
        Xs[lxk + 1][lxm] = xa.y;
        Xs[lxk + 2][lxm] = xa.z;
        Xs[lxk + 3][lxm] = xa.w;
        *(float4*)&Ws[lwk][lwn] =
            *(const float4*)(W + (size_t)(k0 + lwk) * Hh + lwn);
        __syncthreads();

#pragma unroll
        for (int kk = 0; kk < 16; kk++) {
            float4 a = *(const float4*)&Xs[kk][trow];
            float4 b = *(const float4*)&Ws[kk][tcol];
            acc[0][0] += a.x * b.x; acc[0][1] += a.x * b.y;
            acc[0][2] += a.x * b.z; acc[0][3] += a.x * b.w;
            acc[1][0] += a.y * b.x; acc[1][1] += a.y * b.y;
            acc[1][2] += a.y * b.z; acc[1][3] += a.y * b.w;
            acc[2][0] += a.z * b.x; acc[2][1] += a.z * b.y;
            acc[2][2] += a.z * b.z; acc[2][3] += a.z * b.w;
            acc[3][0] += a.w * b.x; acc[3][1] += a.w * b.y;
            acc[3][2] += a.w * b.z; acc[3][3] += a.w * b.w;
        }
        __syncthreads();
    }

#pragma unroll
    for (int i = 0; i < 4; i++) {
        float4 v = make_float4(acc[i][0], acc[i][1], acc[i][2], acc[i][3]);
        *(float4*)(out + (size_t)(m0 + trow + i) * Hh + tcol) = v;
    }
}

// ---------------------------------------------------------------------------
// Kernel 2: causal flash attention over one (batch, 64-query block).
// 256 threads. All mainloop shared loads are float4.
//   Qt[h][i], Kt[h][j] : transposed for the S = Q K^T micro-kernel
//   Vs[j][h]           : natural for the O += P V micro-kernel
//   Ss[q][k]           : raw masked scores (softmax reads rows)
//   Pt[k][q]           : probabilities transposed for the PV micro-kernel
// ---------------------------------------------------------------------------
#define SROW 68
#define SMEM_FLOATS (5 * 64 * SROW + 4 * 64)
#define SMEM_BYTES  (SMEM_FLOATS * 4)

__global__ __launch_bounds__(256) void attn_kernel(
    const float* __restrict__ amask,
    float* __restrict__ out)
{
    extern __shared__ float sm[];
    float* Qt    = sm;
    float* Kt    = Qt + 64 * SROW;
    float* Vs    = Kt + 64 * SROW;
    float* Ss    = Vs + 64 * SROW;
    float* Pt    = Ss + 64 * SROW;
    float* am_sh = Pt + 64 * SROW;
    float* m_sh  = am_sh + 64;
    float* l_sh  = m_sh + 64;
    float* al_sh = l_sh + 64;

    const int b   = blockIdx.y;
    const int q0  = blockIdx.x * 64;
    const int tid = threadIdx.x;

    // Q tile -> Qt[h][i]
    const float* qptr = g_q + ((size_t)b * Tt + q0) * Hh;
#pragma unroll
    for (int r = 0; r < 4; r++) {
        int idx = r * 256 + tid;
        int i   = idx >> 4;
        int h4  = (idx & 15) << 2;
        float4 v = *(const float4*)(qptr + (size_t)i * Hh + h4);
        Qt[(h4 + 0) * SROW + i] = v.x;
        Qt[(h4 + 1) * SROW + i] = v.y;
        Qt[(h4 + 2) * SROW + i] = v.z;
        Qt[(h4 + 3) * SROW + i] = v.w;
    }
    if (tid < 64) {
        am_sh[tid] = amask[(size_t)b * Tt + q0 + tid];
        m_sh[tid]  = -INFINITY;
        l_sh[tid]  = 0.f;
    }

    const int trow = (tid >> 4) << 2;
    const int tcol = (tid & 15) << 2;
    const int lane = tid & 31;
    const int srow = (tid >> 5) * 8 + (lane >> 2);   // softmax row
    const int quad = lane & 3;
    const int c0   = quad * 16;                      // softmax col range

    float o[4][4];
#pragma unroll
    for (int i = 0; i < 4; i++)
#pragma unroll
        for (int j = 0; j < 4; j++) o[i][j] = 0.f;

    __syncthreads();

    for (int j0 = 0; j0 <= q0; j0 += 64) {
        // K tile -> Kt[h][j], V tile -> Vs[j][h]
        const float* kptr = g_k + ((size_t)b * Tt + j0) * Hh;
        const float* vptr = g_v + ((size_t)b * Tt + j0) * Hh;
#pragma unroll
        for (int r = 0; r < 4; r++) {
            int idx = r * 256 + tid;
            int i   = idx >> 4;
            int h4  = (idx & 15) << 2;
            float4 kv = *(const float4*)(kptr + (size_t)i * Hh + h4);
            Kt[(h4 + 0) * SROW + i] = kv.x;
            Kt[(h4 + 1) * SROW + i] = kv.y;
            Kt[(h4 + 2) * SROW + i] = kv.z;
            Kt[(h4 + 3) * SROW + i] = kv.w;
            *(float4*)&Vs[i * SROW + h4] =
                *(const float4*)(vptr + (size_t)i * Hh + h4);
        }
        __syncthreads();

        // S = Q K^T  (4x4 per thread)
        float s[4][4];
#pragma unroll
        for (int i = 0; i < 4; i++)
#pragma unroll
            for (int j = 0; j < 4; j++) s[i][j] = 0.f;
#pragma unroll
        for (int h = 0; h < 64; h++) {
            float4 a  = *(const float4*)&Qt[h * SROW + trow];
            float4 bb = *(const float4*)&Kt[h * SROW + tcol];
            s[0][0] += a.x * bb.x; s[0][1] += a.x * bb.y;
            s[0][2] += a.x * bb.z; s[0][3] += a.x * bb.w;
            s[1][0] += a.y * bb.x; s[1][1] += a.y * bb.y;
            s[1][2] += a.y * bb.z; s[1][3] += a.y * bb.w;
            s[2][0] += a.z * bb.x; s[2][1] += a.z * bb.y;
            s[2][2] += a.z * bb.z; s[2][3] += a.z * bb.w;
            s[3][0] += a.w * bb.x; s[3][1] += a.w * bb.y;
            s[3][2] += a.w * bb.z; s[3][3] += a.w * bb.w;
        }
        // masks: am * s ; s==0 -> -inf ; causal -> -inf
#pragma unroll
        for (int i = 0; i < 4; i++) {
            float amv = am_sh[trow + i];
            int   qg  = q0 + trow + i;
#pragma unroll
            for (int j = 0; j < 4; j++) {
                float val = s[i][j] * 0.125f;   // 1/sqrt(64)
                val *= amv;
                if (val == 0.f) val = -INFINITY;
                if (j0 + tcol + j > qg) val = -INFINITY;
                Ss[(trow + i) * SROW + tcol + j] = val;
            }
        }
        __syncthreads();

        // online softmax: 4 lanes per row, 16 cols per lane
        {
            float vbuf[16];
            float mx = -INFINITY;
#pragma unroll
            for (int c = 0; c < 16; c++) {
                vbuf[c] = Ss[srow * SROW + c0 + c];
                mx = fmaxf(mx, vbuf[c]);
            }
            mx = fmaxf(mx, __shfl_xor_sync(0xffffffffu, mx, 1));
            mx = fmaxf(mx, __shfl_xor_sync(0xffffffffu, mx, 2));
            float m_old = m_sh[srow];
            float m_new = fmaxf(m_old, mx);
            float alpha;
            float lsum = 0.f;
            if (m_new == -INFINITY) {           // fully-masked so far
                alpha = 1.f;
#pragma unroll
                for (int c = 0; c < 16; c++)
                    Pt[(c0 + c) * SROW + srow] = 0.f;
            } else {
                alpha = __expf(m_old - m_new);  // m_old=-inf -> 0
#pragma unroll
                for (int c = 0; c < 16; c++) {
                    float p = __expf(vbuf[c] - m_new);
                    lsum += p;
                    Pt[(c0 + c) * SROW + srow] = p;
                }
            }
            lsum += __shfl_xor_sync(0xffffffffu, lsum, 1);
            lsum += __shfl_xor_sync(0xffffffffu, lsum, 2);
            if (quad == 0) {
                m_sh[srow]  = m_new;
                l_sh[srow]  = l_sh[srow] * alpha + lsum;
                al_sh[srow] = alpha;
            }
        }
        __syncthreads();

        // O = O*alpha + P V
        {
            float a0 = al_sh[trow + 0];
            float a1 = al_sh[trow + 1];
            float a2 = al_sh[trow + 2];
            float a3 = al_sh[trow + 3];
#pragma unroll
            for (int j = 0; j < 4; j++) {
                o[0][j] *= a0; o[1][j] *= a1; o[2][j] *= a2; o[3][j] *= a3;
            }
#pragma unroll
            for (int k = 0; k < 64; k++) {
                float4 p  = *(const float4*)&Pt[k * SROW + trow];
                float4 vv = *(const float4*)&Vs[k * SROW + tcol];
                o[0][0] += p.x * vv.x; o[0][1] += p.x * vv.y;
                o[0][2] += p.x * vv.z; o[0][3] += p.x * vv.w;
                o[1][0] += p.y * vv.x; o[1][1] += p.y * vv.y;
                o[1][2] += p.y * vv.z; o[1][3] += p.y * vv.w;
                o[2][0] += p.z * vv.x; o[2][1] += p.z * vv.y;
                o[2][2] += p.z * vv.z; o[2][3] += p.z * vv.w;
                o[3][0] += p.w * vv.x; o[3][1] += p.w * vv.y;
                o[3][2] += p.w * vv.z; o[3][3] += p.w * vv.w;
            }
        }
        __syncthreads();
    }

    // final: O / l   (l==0 -> fully-masked row -> zeros, matches NaN cleanup)
    float* op = out + ((size_t)b * Tt + q0) * Hh;
#pragma unroll
    for (int i = 0; i < 4; i++) {
        float l   = l_sh[trow + i];
        float inv = (l > 0.f) ? (1.f / l) : 0.f;
        float4 v = make_float4(o[i][0] * inv, o[i][1] * inv,
                               o[i][2] * inv, o[i][3] * inv);
        *(float4*)(op + (size_t)(trow + i) * Hh + tcol) = v;
    }
}

// ---------------------------------------------------------------------------
extern "C" void kernel_launch(void* const* d_in, const int* in_sizes, int n_in,
                              void* d_out, int out_size)
{
    const float* x  = (const float*)d_in[0];
    const float* am = (const float*)d_in[1];
    const float* Wq = (const float*)d_in[2];
    const float* Wk = (const float*)d_in[3];
    const float* Wv = (const float*)d_in[4];
    float*       out = (float*)d_out;

    dim3 g1(M_TOT / 64, 3);
    qkv_proj<<<g1, 256>>>(x, Wq, Wk, Wv);

    cudaFuncSetAttribute(attn_kernel,
                         cudaFuncAttributeMaxDynamicSharedMemorySize,
                         SMEM_BYTES);
    dim3 g2(Tt / 64, Bb);
    attn_kernel<<<g2, 256, SMEM_BYTES>>>(am, out);
}

// round 4
// speedup vs baseline: 1.3013x; 1.3013x over previous
#include <cuda_runtime.h>
#include <math.h>
#include <stdint.h>

#define Bb 8
#define Tt 2048
#define Cc 768
#define Hh 64
#define M_TOT (Bb*Tt)

// scratch
__device__ float g_q[M_TOT*Hh];
__device__ float g_k[M_TOT*Hh];
__device__ float g_v[M_TOT*Hh];
__device__ float g_wt[192*Cc];   // fused transposed weights [n][k]; n: 0-63 q, 64-127 k, 128-191 v

// ---------------------------------------------------------------------------
// helpers: tf32 round + mma.sync (sm_80+ features, safe on plain sm_103 target)
// ---------------------------------------------------------------------------
__device__ __forceinline__ float ftf32(float f) {
    uint32_t u;
    asm("cvt.rna.tf32.f32 %0, %1;" : "=r"(u) : "f"(f));
    return __uint_as_float(u);
}

__device__ __forceinline__ void mma16n8k8(float* d, const float* a,
                                          float b0, float b1) {
    asm volatile(
        "mma.sync.aligned.m16n8k8.row.col.f32.tf32.tf32.f32 "
        "{%0,%1,%2,%3}, {%4,%5,%6,%7}, {%8,%9}, {%0,%1,%2,%3};"
        : "+f"(d[0]), "+f"(d[1]), "+f"(d[2]), "+f"(d[3])
        : "r"(__float_as_uint(a[0])), "r"(__float_as_uint(a[1])),
          "r"(__float_as_uint(a[2])), "r"(__float_as_uint(a[3])),
          "r"(__float_as_uint(b0)),  "r"(__float_as_uint(b1)));
}

// ---------------------------------------------------------------------------
// Kernel 0: transpose+fuse weights into g_wt[n][k]
// ---------------------------------------------------------------------------
__global__ void wtrans(const float* __restrict__ Wq,
                       const float* __restrict__ Wk,
                       const float* __restrict__ Wv)
{
    int idx = blockIdx.x * 256 + threadIdx.x;   // 192*768 = 147456
    int n = idx / Cc, k = idx % Cc;
    const float* W = (n < 64) ? Wq : (n < 128 ? Wk : Wv);
    g_wt[idx] = W[(size_t)k * Hh + (n & 63)];
}

// ---------------------------------------------------------------------------
// Kernel 1: QKV projection via mma.sync tf32.
// CTA tile: 128(M) x 192(N fused), K chunks of 16, double-buffered SMEM.
// 8 warps as 4(M)x2(N): warp tile 32x96 = 2 x 12 m16n8k8 fragments.
// SMEM row stride 20 floats -> fragment LDS provably bank-conflict-free.
// ---------------------------------------------------------------------------
#define BKq 16
#define NTq (Cc / BKq)                           // 48
#define QKV_SMEM ((2*128*20 + 2*192*20) * 4)     // 51200 B

__global__ __launch_bounds__(256) void qkv_mma(const float* __restrict__ x)
{
    extern __shared__ float smq[];
    float* As = smq;                 // [2][128*20]
    float* Bs = smq + 2 * 128 * 20;  // [2][192*20]

    const int tid  = threadIdx.x;
    const int lane = tid & 31, wid = tid >> 5;
    const int m0   = blockIdx.x * 128;
    const int g    = lane >> 2, tig = lane & 3;
    const int wm   = wid & 3,  wn  = wid >> 2;

    int rowA[2], cA[2], rowB[3], cB[3];
#pragma unroll
    for (int r = 0; r < 2; r++) { int idx = r*256+tid; rowA[r]=idx>>2; cA[r]=(idx&3)<<2; }
#pragma unroll
    for (int r = 0; r < 3; r++) { int idx = r*256+tid; rowB[r]=idx>>2; cB[r]=(idx&3)<<2; }

    float acc[2][12][4];
#pragma unroll
    for (int i = 0; i < 2; i++)
#pragma unroll
        for (int j = 0; j < 12; j++)
#pragma unroll
            for (int r = 0; r < 4; r++) acc[i][j][r] = 0.f;

    // prologue: chunk 0 -> buffer 0
#pragma unroll
    for (int r = 0; r < 2; r++) {
        float4 v = *(const float4*)(x + (size_t)(m0 + rowA[r]) * Cc + cA[r]);
        float* d = &As[rowA[r] * 20 + cA[r]];
        d[0]=ftf32(v.x); d[1]=ftf32(v.y); d[2]=ftf32(v.z); d[3]=ftf32(v.w);
    }
#pragma unroll
    for (int r = 0; r < 3; r++) {
        float4 v = *(const float4*)(g_wt + (size_t)rowB[r] * Cc + cB[r]);
        float* d = &Bs[rowB[r] * 20 + cB[r]];
        d[0]=ftf32(v.x); d[1]=ftf32(v.y); d[2]=ftf32(v.z); d[3]=ftf32(v.w);
    }
    __syncthreads();

    for (int t = 0; t < NTq; t++) {
        const int buf = t & 1;
        float4 stA[2], stB[3];
        if (t + 1 < NTq) {
            const int k0 = (t + 1) * BKq;
#pragma unroll
            for (int r = 0; r < 2; r++)
                stA[r] = *(const float4*)(x + (size_t)(m0 + rowA[r]) * Cc + k0 + cA[r]);
#pragma unroll
            for (int r = 0; r < 3; r++)
                stB[r] = *(const float4*)(g_wt + (size_t)rowB[r] * Cc + k0 + cB[r]);
        }

        const float* Asb = As + buf * 128 * 20;
        const float* Bsb = Bs + buf * 192 * 20;
#pragma unroll
        for (int kk = 0; kk < 16; kk += 8) {
            float a[2][4];
#pragma unroll
            for (int i = 0; i < 2; i++) {
                int mr = wm * 32 + i * 16;
                a[i][0] = Asb[(mr + g)     * 20 + kk + tig];
                a[i][1] = Asb[(mr + g + 8) * 20 + kk + tig];
                a[i][2] = Asb[(mr + g)     * 20 + kk + tig + 4];
                a[i][3] = Asb[(mr + g + 8) * 20 + kk + tig + 4];
            }
#pragma unroll
            for (int j = 0; j < 12; j++) {
                int nr = wn * 96 + j * 8 + g;
                float b0 = Bsb[nr * 20 + kk + tig];
                float b1 = Bsb[nr * 20 + kk + tig + 4];
                mma16n8k8(acc[0][j], a[0], b0, b1);
                mma16n8k8(acc[1][j], a[1], b0, b1);
            }
        }

        if (t + 1 < NTq) {
            float* Ad = As + (buf ^ 1) * 128 * 20;
            float* Bd = Bs + (buf ^ 1) * 192 * 20;
#pragma unroll
            for (int r = 0; r < 2; r++) {
                float* d = &Ad[rowA[r] * 20 + cA[r]];
                d[0]=ftf32(stA[r].x); d[1]=ftf32(stA[r].y);
                d[2]=ftf32(stA[r].z); d[3]=ftf32(stA[r].w);
            }
#pragma unroll
            for (int r = 0; r < 3; r++) {
                float* d = &Bd[rowB[r] * 20 + cB[r]];
                d[0]=ftf32(stB[r].x); d[1]=ftf32(stB[r].y);
                d[2]=ftf32(stB[r].z); d[3]=ftf32(stB[r].w);
            }
        }
        __syncthreads();
    }

    // epilogue: D fragment (i,j): rows mf+g, mf+g+8; cols nf + tig*2, +1
#pragma unroll
    for (int i = 0; i < 2; i++) {
        int r0 = m0 + wm * 32 + i * 16 + g;
#pragma unroll
        for (int j = 0; j < 12; j++) {
            int c = wn * 96 + j * 8 + tig * 2;
            float* op = (c < 64) ? g_q : (c < 128 ? g_k : g_v);
            int oc = c & 63;
            *(float2*)(op + (size_t)r0 * Hh + oc) =
                make_float2(acc[i][j][0], acc[i][j][1]);
            *(float2*)(op + (size_t)(r0 + 8) * Hh + oc) =
                make_float2(acc[i][j][2], acc[i][j][3]);
        }
    }
}

// ---------------------------------------------------------------------------
// Kernel 2: causal flash attention, fp32 SIMT.
// Register-resident online softmax: each 64-col row lives in one 16-lane
// half-warp -> shfl_xor(1,2,4,8) row reductions; m/l state in registers.
// smem: Qt,Kt (transposed [h][.]), Vs [k][h], Ps [q][k], am -> ~70KB, occ 2.
// ---------------------------------------------------------------------------
#define AROW 68
#define ATTN_SMEM ((4 * 64 * AROW + 64) * 4)

__global__ __launch_bounds__(256, 2) void attn_kernel(
    const float* __restrict__ amask,
    float* __restrict__ out)
{
    extern __shared__ float sm[];
    float* Qt    = sm;
    float* Kt    = Qt + 64 * AROW;
    float* Vs    = Kt + 64 * AROW;
    float* Ps    = Vs + 64 * AROW;
    float* am_sh = Ps + 64 * AROW;

    const int b   = blockIdx.y;
    const int q0  = ((int)gridDim.x - 1 - (int)blockIdx.x) * 64;  // longest first
    const int tid = threadIdx.x;

    // Q tile -> Qt[h][i]
    const float* qptr = g_q + ((size_t)b * Tt + q0) * Hh;
#pragma unroll
    for (int r = 0; r < 4; r++) {
        int idx = r * 256 + tid;
        int i   = idx >> 4;
        int h4  = (idx & 15) << 2;
        float4 v = *(const float4*)(qptr + (size_t)i * Hh + h4);
        Qt[(h4 + 0) * AROW + i] = v.x;
        Qt[(h4 + 1) * AROW + i] = v.y;
        Qt[(h4 + 2) * AROW + i] = v.z;
        Qt[(h4 + 3) * AROW + i] = v.w;
    }
    if (tid < 64) am_sh[tid] = amask[(size_t)b * Tt + q0 + tid];

    const int trow = (tid >> 4) << 2;   // row group: 16 lanes share trow
    const int tcol = (tid & 15) << 2;

    float m[4], l[4], o[4][4];
#pragma unroll
    for (int i = 0; i < 4; i++) {
        m[i] = -INFINITY; l[i] = 0.f;
#pragma unroll
        for (int j = 0; j < 4; j++) o[i][j] = 0.f;
    }

    __syncthreads();

    for (int j0 = 0; j0 <= q0; j0 += 64) {
        // K tile -> Kt[h][j], V tile -> Vs[j][h]
        const float* kptr = g_k + ((size_t)b * Tt + j0) * Hh;
        const float* vptr = g_v + ((size_t)b * Tt + j0) * Hh;
#pragma unroll
        for (int r = 0; r < 4; r++) {
            int idx = r * 256 + tid;
            int i   = idx >> 4;
            int h4  = (idx & 15) << 2;
            float4 kv = *(const float4*)(kptr + (size_t)i * Hh + h4);
            Kt[(h4 + 0) * AROW + i] = kv.x;
            Kt[(h4 + 1) * AROW + i] = kv.y;
            Kt[(h4 + 2) * AROW + i] = kv.z;
            Kt[(h4 + 3) * AROW + i] = kv.w;
            *(float4*)&Vs[i * AROW + h4] =
                *(const float4*)(vptr + (size_t)i * Hh + h4);
        }
        __syncthreads();

        // S = Q K^T (4x4 per thread)
        float s[4][4];
#pragma unroll
        for (int i = 0; i < 4; i++)
#pragma unroll
            for (int j = 0; j < 4; j++) s[i][j] = 0.f;
#pragma unroll
        for (int h = 0; h < 64; h++) {
            float4 a  = *(const float4*)&Qt[h * AROW + trow];
            float4 bb = *(const float4*)&Kt[h * AROW + tcol];
            s[0][0] += a.x * bb.x; s[0][1] += a.x * bb.y;
            s[0][2] += a.x * bb.z; s[0][3] += a.x * bb.w;
            s[1][0] += a.y * bb.x; s[1][1] += a.y * bb.y;
            s[1][2] += a.y * bb.z; s[1][3] += a.y * bb.w;
            s[2][0] += a.z * bb.x; s[2][1] += a.z * bb.y;
            s[2][2] += a.z * bb.z; s[2][3] += a.z * bb.w;
            s[3][0] += a.w * bb.x; s[3][1] += a.w * bb.y;
            s[3][2] += a.w * bb.z; s[3][3] += a.w * bb.w;
        }

        // masks: am * (s/8) ; ==0 -> -inf ; causal -> -inf
#pragma unroll
        for (int i = 0; i < 4; i++) {
            float amv = am_sh[trow + i];
            int   qg  = q0 + trow + i;
#pragma unroll
            for (int j = 0; j < 4; j++) {
                float val = s[i][j] * 0.125f;
                val *= amv;
                if (val == 0.f) val = -INFINITY;
                if (j0 + tcol + j > qg) val = -INFINITY;
                s[i][j] = val;
            }
        }

        // row max over the 16-lane group
        float mx[4], alpha[4];
#pragma unroll
        for (int i = 0; i < 4; i++) {
            mx[i] = fmaxf(fmaxf(s[i][0], s[i][1]), fmaxf(s[i][2], s[i][3]));
        }
#pragma unroll
        for (int d = 1; d <= 8; d <<= 1) {
#pragma unroll
            for (int i = 0; i < 4; i++)
                mx[i] = fmaxf(mx[i], __shfl_xor_sync(0xffffffffu, mx[i], d));
        }

        // online update, exp in registers
        float ls[4];
#pragma unroll
        for (int i = 0; i < 4; i++) {
            float mn = fmaxf(m[i], mx[i]);
            if (mn == -INFINITY) {
                alpha[i] = 1.f;
#pragma unroll
                for (int j = 0; j < 4; j++) s[i][j] = 0.f;
            } else {
                alpha[i] = __expf(m[i] - mn);
#pragma unroll
                for (int j = 0; j < 4; j++) s[i][j] = __expf(s[i][j] - mn);
            }
            m[i]  = mn;
            ls[i] = (s[i][0] + s[i][1]) + (s[i][2] + s[i][3]);
        }
#pragma unroll
        for (int d = 1; d <= 8; d <<= 1) {
#pragma unroll
            for (int i = 0; i < 4; i++)
                ls[i] += __shfl_xor_sync(0xffffffffu, ls[i], d);
        }
#pragma unroll
        for (int i = 0; i < 4; i++) l[i] = l[i] * alpha[i] + ls[i];

        // P -> smem [q][k]; rescale O
#pragma unroll
        for (int i = 0; i < 4; i++) {
#pragma unroll
            for (int j = 0; j < 4; j++) {
                Ps[(trow + i) * AROW + tcol + j] = s[i][j];
                o[i][j] *= alpha[i];
            }
        }
        __syncthreads();

        // O += P V   (P rows broadcast within the 16-lane group)
#pragma unroll
        for (int k4 = 0; k4 < 16; k4++) {
            float4 p0 = *(const float4*)&Ps[(trow + 0) * AROW + k4 * 4];
            float4 p1 = *(const float4*)&Ps[(trow + 1) * AROW + k4 * 4];
            float4 p2 = *(const float4*)&Ps[(trow + 2) * AROW + k4 * 4];
            float4 p3 = *(const float4*)&Ps[(trow + 3) * AROW + k4 * 4];
            float4 v0 = *(const float4*)&Vs[(k4 * 4 + 0) * AROW + tcol];
            float4 v1 = *(const float4*)&Vs[(k4 * 4 + 1) * AROW + tcol];
            float4 v2 = *(const float4*)&Vs[(k4 * 4 + 2) * AROW + tcol];
            float4 v3 = *(const float4*)&Vs[(k4 * 4 + 3) * AROW + tcol];

            o[0][0] += p0.x*v0.x + p0.y*v1.x + p0.z*v2.x + p0.w*v3.x;
            o[0][1] += p0.x*v0.y + p0.y*v1.y + p0.z*v2.y + p0.w*v3.y;
            o[0][2] += p0.x*v0.z + p0.y*v1.z + p0.z*v2.z + p0.w*v3.z;
            o[0][3] += p0.x*v0.w + p0.y*v1.w + p0.z*v2.w + p0.w*v3.w;
            o[1][0] += p1.x*v0.x + p1.y*v1.x + p1.z*v2.x + p1.w*v3.x;
            o[1][1] += p1.x*v0.y + p1.y*v1.y + p1.z*v2.y + p1.w*v3.y;
            o[1][2] += p1.x*v0.z + p1.y*v1.z + p1.z*v2.z + p1.w*v3.z;
            o[1][3] += p1.x*v0.w + p1.y*v1.w + p1.z*v2.w + p1.w*v3.w;
            o[2][0] += p2.x*v0.x + p2.y*v1.x + p2.z*v2.x + p2.w*v3.x;
            o[2][1] += p2.x*v0.y + p2.y*v1.y + p2.z*v2.y + p2.w*v3.y;
            o[2][2] += p2.x*v0.z + p2.y*v1.z + p2.z*v2.z + p2.w*v3.z;
            o[2][3] += p2.x*v0.w + p2.y*v1.w + p2.z*v2.w + p2.w*v3.w;
            o[3][0] += p3.x*v0.x + p3.y*v1.x + p3.z*v2.x + p3.w*v3.x;
            o[3][1] += p3.x*v0.y + p3.y*v1.y + p3.z*v2.y + p3.w*v3.y;
            o[3][2] += p3.x*v0.z + p3.y*v1.z + p3.z*v2.z + p3.w*v3.z;
            o[3][3] += p3.x*v0.w + p3.y*v1.w + p3.z*v2.w + p3.w*v3.w;
        }
        __syncthreads();
    }

    // final: O / l   (l==0 -> zeros, matches NaN cleanup)
    float* op = out + ((size_t)b * Tt + q0) * Hh;
#pragma unroll
    for (int i = 0; i < 4; i++) {
        float inv = (l[i] > 0.f) ? (1.f / l[i]) : 0.f;
        float4 v = make_float4(o[i][0] * inv, o[i][1] * inv,
                               o[i][2] * inv, o[i][3] * inv);
        *(float4*)(op + (size_t)(trow + i) * Hh + tcol) = v;
    }
}

// ---------------------------------------------------------------------------
extern "C" void kernel_launch(void* const* d_in, const int* in_sizes, int n_in,
                              void* d_out, int out_size)
{
    const float* x  = (const float*)d_in[0];
    const float* am = (const float*)d_in[1];
    const float* Wq = (const float*)d_in[2];
    const float* Wk = (const float*)d_in[3];
    const float* Wv = (const float*)d_in[4];
    float*       out = (float*)d_out;

    wtrans<<<(192 * Cc) / 256, 256>>>(Wq, Wk, Wv);

    cudaFuncSetAttribute(qkv_mma,
                         cudaFuncAttributeMaxDynamicSharedMemorySize, QKV_SMEM);
    qkv_mma<<<M_TOT / 128, 256, QKV_SMEM>>>(x);

    cudaFuncSetAttribute(attn_kernel,
                         cudaFuncAttributeMaxDynamicSharedMemorySize, ATTN_SMEM);
    dim3 g2(Tt / 64, Bb);
    attn_kernel<<<g2, 256, ATTN_SMEM>>>(am, out);
}

// round 5
// speedup vs baseline: 1.3420x; 1.0312x over previous
#include <cuda_runtime.h>
#include <math.h>
#include <stdint.h>

#define Bb 8
#define Tt 2048
#define Cc 768
#define Hh 64
#define M_TOT (Bb*Tt)

typedef unsigned long long ull;

// scratch
__device__ float g_q[M_TOT*Hh];
__device__ float g_k[M_TOT*Hh];
__device__ float g_v[M_TOT*Hh];
__device__ float g_wt[192*Cc];   // fused transposed weights [n][k]; n: 0-63 q, 64-127 k, 128-191 v

// ---------------------------------------------------------------------------
// helpers
// ---------------------------------------------------------------------------
__device__ __forceinline__ float ftf32(float f) {
    uint32_t u;
    asm("cvt.rna.tf32.f32 %0, %1;" : "=r"(u) : "f"(f));
    return __uint_as_float(u);
}

__device__ __forceinline__ void mma16n8k8(float* d, const float* a,
                                          float b0, float b1) {
    asm volatile(
        "mma.sync.aligned.m16n8k8.row.col.f32.tf32.tf32.f32 "
        "{%0,%1,%2,%3}, {%4,%5,%6,%7}, {%8,%9}, {%0,%1,%2,%3};"
        : "+f"(d[0]), "+f"(d[1]), "+f"(d[2]), "+f"(d[3])
        : "r"(__float_as_uint(a[0])), "r"(__float_as_uint(a[1])),
          "r"(__float_as_uint(a[2])), "r"(__float_as_uint(a[3])),
          "r"(__float_as_uint(b0)),  "r"(__float_as_uint(b1)));
}

// packed fp32x2 (Blackwell family-wide)
__device__ __forceinline__ ull pk2(float x, float y) {
    ull r; asm("mov.b64 %0, {%1, %2};" : "=l"(r) : "f"(x), "f"(y)); return r;
}
__device__ __forceinline__ void upk2(ull v, float& x, float& y) {
    asm("mov.b64 {%0, %1}, %2;" : "=f"(x), "=f"(y) : "l"(v));
}
__device__ __forceinline__ void fma2(ull& d, ull a, ull b) {
    asm("fma.rn.f32x2 %0, %1, %2, %0;" : "+l"(d) : "l"(a), "l"(b));
}
__device__ __forceinline__ ull mul2(ull a, ull b) {
    ull d; asm("mul.rn.f32x2 %0, %1, %2;" : "=l"(d) : "l"(a), "l"(b)); return d;
}

// ---------------------------------------------------------------------------
// Kernel 0: transpose+fuse weights into g_wt[n][k]
// ---------------------------------------------------------------------------
__global__ void wtrans(const float* __restrict__ Wq,
                       const float* __restrict__ Wk,
                       const float* __restrict__ Wv)
{
    int idx = blockIdx.x * 256 + threadIdx.x;   // 192*768 = 147456
    int n = idx / Cc, k = idx % Cc;
    const float* W = (n < 64) ? Wq : (n < 128 ? Wk : Wv);
    g_wt[idx] = W[(size_t)k * Hh + (n & 63)];
}

// ---------------------------------------------------------------------------
// Kernel 1: QKV projection via mma.sync tf32 (float4 STS on the fill path).
// ---------------------------------------------------------------------------
#define BKq 16
#define NTq (Cc / BKq)                           // 48
#define QKV_SMEM ((2*128*20 + 2*192*20) * 4)     // 51200 B

__global__ __launch_bounds__(256) void qkv_mma(const float* __restrict__ x)
{
    extern __shared__ float smq[];
    float* As = smq;                 // [2][128*20]
    float* Bs = smq + 2 * 128 * 20;  // [2][192*20]

    const int tid  = threadIdx.x;
    const int lane = tid & 31, wid = tid >> 5;
    const int m0   = blockIdx.x * 128;
    const int g    = lane >> 2, tig = lane & 3;
    const int wm   = wid & 3,  wn  = wid >> 2;

    int rowA[2], cA[2], rowB[3], cB[3];
#pragma unroll
    for (int r = 0; r < 2; r++) { int idx = r*256+tid; rowA[r]=idx>>2; cA[r]=(idx&3)<<2; }
#pragma unroll
    for (int r = 0; r < 3; r++) { int idx = r*256+tid; rowB[r]=idx>>2; cB[r]=(idx&3)<<2; }

    float acc[2][12][4];
#pragma unroll
    for (int i = 0; i < 2; i++)
#pragma unroll
        for (int j = 0; j < 12; j++)
#pragma unroll
            for (int r = 0; r < 4; r++) acc[i][j][r] = 0.f;

    // prologue: chunk 0 -> buffer 0
#pragma unroll
    for (int r = 0; r < 2; r++) {
        float4 v = *(const float4*)(x + (size_t)(m0 + rowA[r]) * Cc + cA[r]);
        float4 w = make_float4(ftf32(v.x), ftf32(v.y), ftf32(v.z), ftf32(v.w));
        *(float4*)&As[rowA[r] * 20 + cA[r]] = w;
    }
#pragma unroll
    for (int r = 0; r < 3; r++) {
        float4 v = *(const float4*)(g_wt + (size_t)rowB[r] * Cc + cB[r]);
        float4 w = make_float4(ftf32(v.x), ftf32(v.y), ftf32(v.z), ftf32(v.w));
        *(float4*)&Bs[rowB[r] * 20 + cB[r]] = w;
    }
    __syncthreads();

    for (int t = 0; t < NTq; t++) {
        const int buf = t & 1;
        float4 stA[2], stB[3];
        if (t + 1 < NTq) {
            const int k0 = (t + 1) * BKq;
#pragma unroll
            for (int r = 0; r < 2; r++)
                stA[r] = *(const float4*)(x + (size_t)(m0 + rowA[r]) * Cc + k0 + cA[r]);
#pragma unroll
            for (int r = 0; r < 3; r++)
                stB[r] = *(const float4*)(g_wt + (size_t)rowB[r] * Cc + k0 + cB[r]);
        }

        const float* Asb = As + buf * 128 * 20;
        const float* Bsb = Bs + buf * 192 * 20;
#pragma unroll
        for (int kk = 0; kk < 16; kk += 8) {
            float a[2][4];
#pragma unroll
            for (int i = 0; i < 2; i++) {
                int mr = wm * 32 + i * 16;
                a[i][0] = Asb[(mr + g)     * 20 + kk + tig];
                a[i][1] = Asb[(mr + g + 8) * 20 + kk + tig];
                a[i][2] = Asb[(mr + g)     * 20 + kk + tig + 4];
                a[i][3] = Asb[(mr + g + 8) * 20 + kk + tig + 4];
            }
#pragma unroll
            for (int j = 0; j < 12; j++) {
                int nr = wn * 96 + j * 8 + g;
                float b0 = Bsb[nr * 20 + kk + tig];
                float b1 = Bsb[nr * 20 + kk + tig + 4];
                mma16n8k8(acc[0][j], a[0], b0, b1);
                mma16n8k8(acc[1][j], a[1], b0, b1);
            }
        }

        if (t + 1 < NTq) {
            float* Ad = As + (buf ^ 1) * 128 * 20;
            float* Bd = Bs + (buf ^ 1) * 192 * 20;
#pragma unroll
            for (int r = 0; r < 2; r++) {
                float4 w = make_float4(ftf32(stA[r].x), ftf32(stA[r].y),
                                       ftf32(stA[r].z), ftf32(stA[r].w));
                *(float4*)&Ad[rowA[r] * 20 + cA[r]] = w;
            }
#pragma unroll
            for (int r = 0; r < 3; r++) {
                float4 w = make_float4(ftf32(stB[r].x), ftf32(stB[r].y),
                                       ftf32(stB[r].z), ftf32(stB[r].w));
                *(float4*)&Bd[rowB[r] * 20 + cB[r]] = w;
            }
        }
        __syncthreads();
    }

#pragma unroll
    for (int i = 0; i < 2; i++) {
        int r0 = m0 + wm * 32 + i * 16 + g;
#pragma unroll
        for (int j = 0; j < 12; j++) {
            int c = wn * 96 + j * 8 + tig * 2;
            float* op = (c < 64) ? g_q : (c < 128 ? g_k : g_v);
            int oc = c & 63;
            *(float2*)(op + (size_t)r0 * Hh + oc) =
                make_float2(acc[i][j][0], acc[i][j][1]);
            *(float2*)(op + (size_t)(r0 + 8) * Hh + oc) =
                make_float2(acc[i][j][2], acc[i][j][3]);
        }
    }
}

// ---------------------------------------------------------------------------
// Kernel 2: causal flash attention, packed f32x2 math.
// S and PV inner loops use fma.rn.f32x2: accumulators are (j,j+1) pairs,
// K/V operands load as ulonglong2 views of the 128-bit LDS, broadcast
// operand packed via mov.b64 (ALU pipe).
// ---------------------------------------------------------------------------
#define AROW 68
#define ATTN_SMEM ((4 * 64 * AROW + 64) * 4)

__global__ __launch_bounds__(256, 2) void attn_kernel(
    const float* __restrict__ amask,
    float* __restrict__ out)
{
    extern __shared__ float sm[];
    float* Qt    = sm;
    float* Kt    = Qt + 64 * AROW;
    float* Vs    = Kt + 64 * AROW;
    float* Ps    = Vs + 64 * AROW;
    float* am_sh = Ps + 64 * AROW;

    const int b   = blockIdx.y;
    const int q0  = ((int)gridDim.x - 1 - (int)blockIdx.x) * 64;  // longest first
    const int tid = threadIdx.x;

    // Q tile -> Qt[h][i]
    const float* qptr = g_q + ((size_t)b * Tt + q0) * Hh;
#pragma unroll
    for (int r = 0; r < 4; r++) {
        int idx = r * 256 + tid;
        int i   = idx >> 4;
        int h4  = (idx & 15) << 2;
        float4 v = *(const float4*)(qptr + (size_t)i * Hh + h4);
        Qt[(h4 + 0) * AROW + i] = v.x;
        Qt[(h4 + 1) * AROW + i] = v.y;
        Qt[(h4 + 2) * AROW + i] = v.z;
        Qt[(h4 + 3) * AROW + i] = v.w;
    }
    if (tid < 64) am_sh[tid] = amask[(size_t)b * Tt + q0 + tid];

    const int trow = (tid >> 4) << 2;   // row group: 16 lanes share trow
    const int tcol = (tid & 15) << 2;

    float m[4], l[4];
    ull o2[4][2];
#pragma unroll
    for (int i = 0; i < 4; i++) {
        m[i] = -INFINITY; l[i] = 0.f;
        o2[i][0] = 0ull; o2[i][1] = 0ull;
    }

    __syncthreads();

    for (int j0 = 0; j0 <= q0; j0 += 64) {
        // K tile -> Kt[h][j], V tile -> Vs[j][h]
        const float* kptr = g_k + ((size_t)b * Tt + j0) * Hh;
        const float* vptr = g_v + ((size_t)b * Tt + j0) * Hh;
#pragma unroll
        for (int r = 0; r < 4; r++) {
            int idx = r * 256 + tid;
            int i   = idx >> 4;
            int h4  = (idx & 15) << 2;
            float4 kv = *(const float4*)(kptr + (size_t)i * Hh + h4);
            Kt[(h4 + 0) * AROW + i] = kv.x;
            Kt[(h4 + 1) * AROW + i] = kv.y;
            Kt[(h4 + 2) * AROW + i] = kv.z;
            Kt[(h4 + 3) * AROW + i] = kv.w;
            *(float4*)&Vs[i * AROW + h4] =
                *(const float4*)(vptr + (size_t)i * Hh + h4);
        }
        __syncthreads();

        // S = Q K^T, packed pairs along j
        ull s2[4][2];
#pragma unroll
        for (int i = 0; i < 4; i++) { s2[i][0] = 0ull; s2[i][1] = 0ull; }
#pragma unroll
        for (int h = 0; h < 64; h++) {
            float4 a = *(const float4*)&Qt[h * AROW + trow];
            ulonglong2 bb = *(const ulonglong2*)&Kt[h * AROW + tcol];
            ull t;
            t = pk2(a.x, a.x); fma2(s2[0][0], t, bb.x); fma2(s2[0][1], t, bb.y);
            t = pk2(a.y, a.y); fma2(s2[1][0], t, bb.x); fma2(s2[1][1], t, bb.y);
            t = pk2(a.z, a.z); fma2(s2[2][0], t, bb.x); fma2(s2[2][1], t, bb.y);
            t = pk2(a.w, a.w); fma2(s2[3][0], t, bb.x); fma2(s2[3][1], t, bb.y);
        }
        float s[4][4];
#pragma unroll
        for (int i = 0; i < 4; i++) {
            upk2(s2[i][0], s[i][0], s[i][1]);
            upk2(s2[i][1], s[i][2], s[i][3]);
        }

        // masks: am * (s/8) ; ==0 -> -inf ; causal -> -inf
#pragma unroll
        for (int i = 0; i < 4; i++) {
            float amv = am_sh[trow + i];
            int   qg  = q0 + trow + i;
#pragma unroll
            for (int j = 0; j < 4; j++) {
                float val = s[i][j] * 0.125f;
                val *= amv;
                if (val == 0.f) val = -INFINITY;
                if (j0 + tcol + j > qg) val = -INFINITY;
                s[i][j] = val;
            }
        }

        // row max over the 16-lane group
        float mx[4], alpha[4];
#pragma unroll
        for (int i = 0; i < 4; i++)
            mx[i] = fmaxf(fmaxf(s[i][0], s[i][1]), fmaxf(s[i][2], s[i][3]));
#pragma unroll
        for (int d = 1; d <= 8; d <<= 1) {
#pragma unroll
            for (int i = 0; i < 4; i++)
                mx[i] = fmaxf(mx[i], __shfl_xor_sync(0xffffffffu, mx[i], d));
        }

        // online update, exp in registers
        float ls[4];
#pragma unroll
        for (int i = 0; i < 4; i++) {
            float mn = fmaxf(m[i], mx[i]);
            if (mn == -INFINITY) {
                alpha[i] = 1.f;
#pragma unroll
                for (int j = 0; j < 4; j++) s[i][j] = 0.f;
            } else {
                alpha[i] = __expf(m[i] - mn);
#pragma unroll
                for (int j = 0; j < 4; j++) s[i][j] = __expf(s[i][j] - mn);
            }
            m[i]  = mn;
            ls[i] = (s[i][0] + s[i][1]) + (s[i][2] + s[i][3]);
        }
#pragma unroll
        for (int d = 1; d <= 8; d <<= 1) {
#pragma unroll
            for (int i = 0; i < 4; i++)
                ls[i] += __shfl_xor_sync(0xffffffffu, ls[i], d);
        }
#pragma unroll
        for (int i = 0; i < 4; i++) l[i] = l[i] * alpha[i] + ls[i];

        // P -> smem [q][k]; rescale O (packed)
#pragma unroll
        for (int i = 0; i < 4; i++) {
            *(float4*)&Ps[(trow + i) * AROW + tcol] =
                make_float4(s[i][0], s[i][1], s[i][2], s[i][3]);
            ull al = pk2(alpha[i], alpha[i]);
            o2[i][0] = mul2(o2[i][0], al);
            o2[i][1] = mul2(o2[i][1], al);
        }
        __syncthreads();

        // O += P V, packed pairs along the h (output) dim
#pragma unroll
        for (int k4 = 0; k4 < 16; k4++) {
            float4 p0 = *(const float4*)&Ps[(trow + 0) * AROW + k4 * 4];
            float4 p1 = *(const float4*)&Ps[(trow + 1) * AROW + k4 * 4];
            float4 p2 = *(const float4*)&Ps[(trow + 2) * AROW + k4 * 4];
            float4 p3 = *(const float4*)&Ps[(trow + 3) * AROW + k4 * 4];
            ulonglong2 v0 = *(const ulonglong2*)&Vs[(k4 * 4 + 0) * AROW + tcol];
            ulonglong2 v1 = *(const ulonglong2*)&Vs[(k4 * 4 + 1) * AROW + tcol];
            ulonglong2 v2 = *(const ulonglong2*)&Vs[(k4 * 4 + 2) * AROW + tcol];
            ulonglong2 v3 = *(const ulonglong2*)&Vs[(k4 * 4 + 3) * AROW + tcol];
            ull t;
            t = pk2(p0.x, p0.x); fma2(o2[0][0], t, v0.x); fma2(o2[0][1], t, v0.y);
            t = pk2(p0.y, p0.y); fma2(o2[0][0], t, v1.x); fma2(o2[0][1], t, v1.y);
            t = pk2(p0.z, p0.z); fma2(o2[0][0], t, v2.x); fma2(o2[0][1], t, v2.y);
            t = pk2(p0.w, p0.w); fma2(o2[0][0], t, v3.x); fma2(o2[0][1], t, v3.y);
            t = pk2(p1.x, p1.x); fma2(o2[1][0], t, v0.x); fma2(o2[1][1], t, v0.y);
            t = pk2(p1.y, p1.y); fma2(o2[1][0], t, v1.x); fma2(o2[1][1], t, v1.y);
            t = pk2(p1.z, p1.z); fma2(o2[1][0], t, v2.x); fma2(o2[1][1], t, v2.y);
            t = pk2(p1.w, p1.w); fma2(o2[1][0], t, v3.x); fma2(o2[1][1], t, v3.y);
            t = pk2(p2.x, p2.x); fma2(o2[2][0], t, v0.x); fma2(o2[2][1], t, v0.y);
            t = pk2(p2.y, p2.y); fma2(o2[2][0], t, v1.x); fma2(o2[2][1], t, v1.y);
            t = pk2(p2.z, p2.z); fma2(o2[2][0], t, v2.x); fma2(o2[2][1], t, v2.y);
            t = pk2(p2.w, p2.w); fma2(o2[2][0], t, v3.x); fma2(o2[2][1], t, v3.y);
            t = pk2(p3.x, p3.x); fma2(o2[3][0], t, v0.x); fma2(o2[3][1], t, v0.y);
            t = pk2(p3.y, p3.y); fma2(o2[3][0], t, v1.x); fma2(o2[3][1], t, v1.y);
            t = pk2(p3.z, p3.z); fma2(o2[3][0], t, v2.x); fma2(o2[3][1], t, v2.y);
            t = pk2(p3.w, p3.w); fma2(o2[3][0], t, v3.x); fma2(o2[3][1], t, v3.y);
        }
        __syncthreads();
    }

    // final: O / l   (l==0 -> zeros, matches NaN cleanup)
    float* op = out + ((size_t)b * Tt + q0) * Hh;
#pragma unroll
    for (int i = 0; i < 4; i++) {
        float inv = (l[i] > 0.f) ? (1.f / l[i]) : 0.f;
        float o0, o1, o2f, o3;
        upk2(o2[i][0], o0, o1);
        upk2(o2[i][1], o2f, o3);
        float4 v = make_float4(o0 * inv, o1 * inv, o2f * inv, o3 * inv);
        *(float4*)(op + (size_t)(trow + i) * Hh + tcol) = v;
    }
}

// ---------------------------------------------------------------------------
extern "C" void kernel_launch(void* const* d_in, const int* in_sizes, int n_in,
                              void* d_out, int out_size)
{
    const float* x  = (const float*)d_in[0];
    const float* am = (const float*)d_in[1];
    const float* Wq = (const float*)d_in[2];
    const float* Wk = (const float*)d_in[3];
    const float* Wv = (const float*)d_in[4];
    float*       out = (float*)d_out;

    wtrans<<<(192 * Cc) / 256, 256>>>(Wq, Wk, Wv);

    cudaFuncSetAttribute(qkv_mma,
                         cudaFuncAttributeMaxDynamicSharedMemorySize, QKV_SMEM);
    qkv_mma<<<M_TOT / 128, 256, QKV_SMEM>>>(x);

    cudaFuncSetAttribute(attn_kernel,
                         cudaFuncAttributeMaxDynamicSharedMemorySize, ATTN_SMEM);
    dim3 g2(Tt / 64, Bb);
    attn_kernel<<<g2, 256, ATTN_SMEM>>>(am, out);
}

// round 6
// speedup vs baseline: 1.3502x; 1.0062x over previous
#include <cuda_runtime.h>
#include <cuda_fp16.h>
#include <math.h>
#include <stdint.h>

#define Bb 8
#define Tt 2048
#define Cc 768
#define Hh 64
#define M_TOT (Bb*Tt)

typedef unsigned long long ull;

// scratch
__device__ float g_q[M_TOT*Hh];
__device__ float g_k[M_TOT*Hh];
__device__ float g_v[M_TOT*Hh];
__device__ float g_wt[192*Cc];   // fused transposed weights [n][k]; n: 0-63 q, 64-127 k, 128-191 v

// ---------------------------------------------------------------------------
// helpers
// ---------------------------------------------------------------------------
__device__ __forceinline__ void mma_fp16(float* d, const uint32_t* a,
                                         uint32_t b0, uint32_t b1) {
    asm volatile(
        "mma.sync.aligned.m16n8k16.row.col.f32.f16.f16.f32 "
        "{%0,%1,%2,%3}, {%4,%5,%6,%7}, {%8,%9}, {%0,%1,%2,%3};"
        : "+f"(d[0]), "+f"(d[1]), "+f"(d[2]), "+f"(d[3])
        : "r"(a[0]), "r"(a[1]), "r"(a[2]), "r"(a[3]), "r"(b0), "r"(b1));
}

// packed fp32x2 (Blackwell family-wide)
__device__ __forceinline__ ull pk2(float x, float y) {
    ull r; asm("mov.b64 %0, {%1, %2};" : "=l"(r) : "f"(x), "f"(y)); return r;
}
__device__ __forceinline__ void upk2(ull v, float& x, float& y) {
    asm("mov.b64 {%0, %1}, %2;" : "=f"(x), "=f"(y) : "l"(v));
}
__device__ __forceinline__ void fma2(ull& d, ull a, ull b) {
    asm("fma.rn.f32x2 %0, %1, %2, %0;" : "+l"(d) : "l"(a), "l"(b));
}
__device__ __forceinline__ ull mul2(ull a, ull b) {
    ull d; asm("mul.rn.f32x2 %0, %1, %2;" : "=l"(d) : "l"(a), "l"(b)); return d;
}

// split a float4 into hi/lo half2 pairs
__device__ __forceinline__ void cvt4(float4 v, uint32_t& h01, uint32_t& h23,
                                     uint32_t& l01, uint32_t& l23) {
    __half2 h0 = __floats2half2_rn(v.x, v.y);
    __half2 h1 = __floats2half2_rn(v.z, v.w);
    float lx = v.x - __half2float(__low2half(h0));
    float ly = v.y - __half2float(__high2half(h0));
    float lz = v.z - __half2float(__low2half(h1));
    float lw = v.w - __half2float(__high2half(h1));
    __half2 l0 = __floats2half2_rn(lx, ly);
    __half2 l1 = __floats2half2_rn(lz, lw);
    h01 = *(uint32_t*)&h0; h23 = *(uint32_t*)&h1;
    l01 = *(uint32_t*)&l0; l23 = *(uint32_t*)&l1;
}

// ---------------------------------------------------------------------------
// Kernel 0: transpose+fuse weights into g_wt[n][k]
// ---------------------------------------------------------------------------
__global__ void wtrans(const float* __restrict__ Wq,
                       const float* __restrict__ Wk,
                       const float* __restrict__ Wv)
{
    int idx = blockIdx.x * 256 + threadIdx.x;   // 192*768 = 147456
    int n = idx / Cc, k = idx % Cc;
    const float* W = (n < 64) ? Wq : (n < 128 ? Wk : Wv);
    g_wt[idx] = W[(size_t)k * Hh + (n & 63)];
}

// ---------------------------------------------------------------------------
// Kernel 1: QKV projection via split-fp16 mma.sync (3-pass: hh + hl + lh).
// CTA tile 128(M) x 192(N fused), BK=32, double-buffered fp16 smem.
// smem rows padded to 40 fp16 (20 words): fragment LDS conflict-free.
// 8 warps as 4(M)x2(N): warp tile 32x96 = 2 x 12 m16n8k16 fragments.
// ---------------------------------------------------------------------------
#define BKh 32
#define NCH (Cc / BKh)         // 24
// word (u32) offsets inside dynamic smem
#define W_AH 0                 // [2][128*20]
#define W_AL 5120
#define W_BH 10240             // [2][192*20]
#define W_BL 17920
#define QKV_SMEM (25600 * 4)   // 102400 B

__global__ __launch_bounds__(256) void qkv_h(const float* __restrict__ x)
{
    extern __shared__ uint32_t smw[];

    const int tid  = threadIdx.x;
    const int lane = tid & 31, wid = tid >> 5;
    const int m0   = blockIdx.x * 128;
    const int g    = lane >> 2, tig = lane & 3;
    const int wm   = wid & 3,  wn  = wid >> 2;

    // load mappings (per chunk): A 4 float4/thread, B 6 float4/thread
    int rowA[4], cA[4], rowB[6], cB[6];
#pragma unroll
    for (int r = 0; r < 4; r++) { int idx = r*256+tid; rowA[r]=idx>>3; cA[r]=(idx&7)<<2; }
#pragma unroll
    for (int r = 0; r < 6; r++) { int idx = r*256+tid; rowB[r]=idx>>3; cB[r]=(idx&7)<<2; }

    float acc[2][12][4];
#pragma unroll
    for (int i = 0; i < 2; i++)
#pragma unroll
        for (int j = 0; j < 12; j++)
#pragma unroll
            for (int r = 0; r < 4; r++) acc[i][j][r] = 0.f;

    // prologue: chunk 0 -> buffer 0
#pragma unroll
    for (int r = 0; r < 4; r++) {
        float4 v = *(const float4*)(x + (size_t)(m0 + rowA[r]) * Cc + cA[r]);
        uint32_t h01, h23, l01, l23; cvt4(v, h01, h23, l01, l23);
        int wi = rowA[r] * 20 + (cA[r] >> 1);
        *(uint2*)&smw[W_AH + wi] = make_uint2(h01, h23);
        *(uint2*)&smw[W_AL + wi] = make_uint2(l01, l23);
    }
#pragma unroll
    for (int r = 0; r < 6; r++) {
        float4 v = *(const float4*)(g_wt + (size_t)rowB[r] * Cc + cB[r]);
        uint32_t h01, h23, l01, l23; cvt4(v, h01, h23, l01, l23);
        int wi = rowB[r] * 20 + (cB[r] >> 1);
        *(uint2*)&smw[W_BH + wi] = make_uint2(h01, h23);
        *(uint2*)&smw[W_BL + wi] = make_uint2(l01, l23);
    }
    __syncthreads();

    for (int t = 0; t < NCH; t++) {
        const int buf = t & 1;
        float4 stA[4], stB[6];
        if (t + 1 < NCH) {
            const int k0 = (t + 1) * BKh;
#pragma unroll
            for (int r = 0; r < 4; r++)
                stA[r] = *(const float4*)(x + (size_t)(m0 + rowA[r]) * Cc + k0 + cA[r]);
#pragma unroll
            for (int r = 0; r < 6; r++)
                stB[r] = *(const float4*)(g_wt + (size_t)rowB[r] * Cc + k0 + cB[r]);
        }

        const uint32_t* Ah = smw + W_AH + buf * 2560;
        const uint32_t* Al = smw + W_AL + buf * 2560;
        const uint32_t* Bh = smw + W_BH + buf * 3840;
        const uint32_t* Bl = smw + W_BL + buf * 3840;

#pragma unroll
        for (int kk2 = 0; kk2 < 16; kk2 += 8) {   // two k16 steps (word offset)
            uint32_t ah[2][4], al[2][4];
#pragma unroll
            for (int i = 0; i < 2; i++) {
                int r0 = (wm * 32 + i * 16 + g) * 20 + kk2 + tig;
                ah[i][0] = Ah[r0];        ah[i][1] = Ah[r0 + 160];
                ah[i][2] = Ah[r0 + 4];    ah[i][3] = Ah[r0 + 164];
                al[i][0] = Al[r0];        al[i][1] = Al[r0 + 160];
                al[i][2] = Al[r0 + 4];    al[i][3] = Al[r0 + 164];
            }
#pragma unroll
            for (int j = 0; j < 12; j++) {
                int nb = (wn * 96 + j * 8 + g) * 20 + kk2 + tig;
                uint32_t bh0 = Bh[nb], bh1 = Bh[nb + 4];
                uint32_t bl0 = Bl[nb], bl1 = Bl[nb + 4];
                mma_fp16(acc[0][j], ah[0], bh0, bh1);
                mma_fp16(acc[1][j], ah[1], bh0, bh1);
                mma_fp16(acc[0][j], ah[0], bl0, bl1);
                mma_fp16(acc[1][j], ah[1], bl0, bl1);
                mma_fp16(acc[0][j], al[0], bh0, bh1);
                mma_fp16(acc[1][j], al[1], bh0, bh1);
            }
        }

        if (t + 1 < NCH) {
            uint32_t* Ahd = smw + W_AH + (buf ^ 1) * 2560;
            uint32_t* Ald = smw + W_AL + (buf ^ 1) * 2560;
            uint32_t* Bhd = smw + W_BH + (buf ^ 1) * 3840;
            uint32_t* Bld = smw + W_BL + (buf ^ 1) * 3840;
#pragma unroll
            for (int r = 0; r < 4; r++) {
                uint32_t h01, h23, l01, l23; cvt4(stA[r], h01, h23, l01, l23);
                int wi = rowA[r] * 20 + (cA[r] >> 1);
                *(uint2*)&Ahd[wi] = make_uint2(h01, h23);
                *(uint2*)&Ald[wi] = make_uint2(l01, l23);
            }
#pragma unroll
            for (int r = 0; r < 6; r++) {
                uint32_t h01, h23, l01, l23; cvt4(stB[r], h01, h23, l01, l23);
                int wi = rowB[r] * 20 + (cB[r] >> 1);
                *(uint2*)&Bhd[wi] = make_uint2(h01, h23);
                *(uint2*)&Bld[wi] = make_uint2(l01, l23);
            }
        }
        __syncthreads();
    }

    // epilogue: fragment (i,j): rows r0, r0+8; cols c, c+1
#pragma unroll
    for (int i = 0; i < 2; i++) {
        int r0 = m0 + wm * 32 + i * 16 + g;
#pragma unroll
        for (int j = 0; j < 12; j++) {
            int c = wn * 96 + j * 8 + tig * 2;
            float* op = (c < 64) ? g_q : (c < 128 ? g_k : g_v);
            int oc = c & 63;
            *(float2*)(op + (size_t)r0 * Hh + oc) =
                make_float2(acc[i][j][0], acc[i][j][1]);
            *(float2*)(op + (size_t)(r0 + 8) * Hh + oc) =
                make_float2(acc[i][j][2], acc[i][j][3]);
        }
    }
}

// ---------------------------------------------------------------------------
// Kernel 2: causal flash attention, packed f32x2 math (unchanged from R5).
// ---------------------------------------------------------------------------
#define AROW 68
#define ATTN_SMEM ((4 * 64 * AROW + 64) * 4)

__global__ __launch_bounds__(256, 2) void attn_kernel(
    const float* __restrict__ amask,
    float* __restrict__ out)
{
    extern __shared__ float sm[];
    float* Qt    = sm;
    float* Kt    = Qt + 64 * AROW;
    float* Vs    = Kt + 64 * AROW;
    float* Ps    = Vs + 64 * AROW;
    float* am_sh = Ps + 64 * AROW;

    const int b   = blockIdx.y;
    const int q0  = ((int)gridDim.x - 1 - (int)blockIdx.x) * 64;  // longest first
    const int tid = threadIdx.x;

    const float* qptr = g_q + ((size_t)b * Tt + q0) * Hh;
#pragma unroll
    for (int r = 0; r < 4; r++) {
        int idx = r * 256 + tid;
        int i   = idx >> 4;
        int h4  = (idx & 15) << 2;
        float4 v = *(const float4*)(qptr + (size_t)i * Hh + h4);
        Qt[(h4 + 0) * AROW + i] = v.x;
        Qt[(h4 + 1) * AROW + i] = v.y;
        Qt[(h4 + 2) * AROW + i] = v.z;
        Qt[(h4 + 3) * AROW + i] = v.w;
    }
    if (tid < 64) am_sh[tid] = amask[(size_t)b * Tt + q0 + tid];

    const int trow = (tid >> 4) << 2;
    const int tcol = (tid & 15) << 2;

    float m[4], l[4];
    ull o2[4][2];
#pragma unroll
    for (int i = 0; i < 4; i++) {
        m[i] = -INFINITY; l[i] = 0.f;
        o2[i][0] = 0ull; o2[i][1] = 0ull;
    }

    __syncthreads();

    for (int j0 = 0; j0 <= q0; j0 += 64) {
        const float* kptr = g_k + ((size_t)b * Tt + j0) * Hh;
        const float* vptr = g_v + ((size_t)b * Tt + j0) * Hh;
#pragma unroll
        for (int r = 0; r < 4; r++) {
            int idx = r * 256 + tid;
            int i   = idx >> 4;
            int h4  = (idx & 15) << 2;
            float4 kv = *(const float4*)(kptr + (size_t)i * Hh + h4);
            Kt[(h4 + 0) * AROW + i] = kv.x;
            Kt[(h4 + 1) * AROW + i] = kv.y;
            Kt[(h4 + 2) * AROW + i] = kv.z;
            Kt[(h4 + 3) * AROW + i] = kv.w;
            *(float4*)&Vs[i * AROW + h4] =
                *(const float4*)(vptr + (size_t)i * Hh + h4);
        }
        __syncthreads();

        ull s2[4][2];
#pragma unroll
        for (int i = 0; i < 4; i++) { s2[i][0] = 0ull; s2[i][1] = 0ull; }
#pragma unroll
        for (int h = 0; h < 64; h++) {
            float4 a = *(const float4*)&Qt[h * AROW + trow];
            ulonglong2 bb = *(const ulonglong2*)&Kt[h * AROW + tcol];
            ull t;
            t = pk2(a.x, a.x); fma2(s2[0][0], t, bb.x); fma2(s2[0][1], t, bb.y);
            t = pk2(a.y, a.y); fma2(s2[1][0], t, bb.x); fma2(s2[1][1], t, bb.y);
            t = pk2(a.z, a.z); fma2(s2[2][0], t, bb.x); fma2(s2[2][1], t, bb.y);
            t = pk2(a.w, a.w); fma2(s2[3][0], t, bb.x); fma2(s2[3][1], t, bb.y);
        }
        float s[4][4];
#pragma unroll
        for (int i = 0; i < 4; i++) {
            upk2(s2[i][0], s[i][0], s[i][1]);
            upk2(s2[i][1], s[i][2], s[i][3]);
        }

#pragma unroll
        for (int i = 0; i < 4; i++) {
            float amv = am_sh[trow + i];
            int   qg  = q0 + trow + i;
#pragma unroll
            for (int j = 0; j < 4; j++) {
                float val = s[i][j] * 0.125f;
                val *= amv;
                if (val == 0.f) val = -INFINITY;
                if (j0 + tcol + j > qg) val = -INFINITY;
                s[i][j] = val;
            }
        }

        float mx[4], alpha[4];
#pragma unroll
        for (int i = 0; i < 4; i++)
            mx[i] = fmaxf(fmaxf(s[i][0], s[i][1]), fmaxf(s[i][2], s[i][3]));
#pragma unroll
        for (int d = 1; d <= 8; d <<= 1) {
#pragma unroll
            for (int i = 0; i < 4; i++)
                mx[i] = fmaxf(mx[i], __shfl_xor_sync(0xffffffffu, mx[i], d));
        }

        float ls[4];
#pragma unroll
        for (int i = 0; i < 4; i++) {
            float mn = fmaxf(m[i], mx[i]);
            if (mn == -INFINITY) {
                alpha[i] = 1.f;
#pragma unroll
                for (int j = 0; j < 4; j++) s[i][j] = 0.f;
            } else {
                alpha[i] = __expf(m[i] - mn);
#pragma unroll
                for (int j = 0; j < 4; j++) s[i][j] = __expf(s[i][j] - mn);
            }
            m[i]  = mn;
            ls[i] = (s[i][0] + s[i][1]) + (s[i][2] + s[i][3]);
        }
#pragma unroll
        for (int d = 1; d <= 8; d <<= 1) {
#pragma unroll
            for (int i = 0; i < 4; i++)
                ls[i] += __shfl_xor_sync(0xffffffffu, ls[i], d);
        }
#pragma unroll
        for (int i = 0; i < 4; i++) l[i] = l[i] * alpha[i] + ls[i];

#pragma unroll
        for (int i = 0; i < 4; i++) {
            *(float4*)&Ps[(trow + i) * AROW + tcol] =
                make_float4(s[i][0], s[i][1], s[i][2], s[i][3]);
            ull al = pk2(alpha[i], alpha[i]);
            o2[i][0] = mul2(o2[i][0], al);
            o2[i][1] = mul2(o2[i][1], al);
        }
        __syncthreads();

#pragma unroll
        for (int k4 = 0; k4 < 16; k4++) {
            float4 p0 = *(const float4*)&Ps[(trow + 0) * AROW + k4 * 4];
            float4 p1 = *(const float4*)&Ps[(trow + 1) * AROW + k4 * 4];
            float4 p2 = *(const float4*)&Ps[(trow + 2) * AROW + k4 * 4];
            float4 p3 = *(const float4*)&Ps[(trow + 3) * AROW + k4 * 4];
            ulonglong2 v0 = *(const ulonglong2*)&Vs[(k4 * 4 + 0) * AROW + tcol];
            ulonglong2 v1 = *(const ulonglong2*)&Vs[(k4 * 4 + 1) * AROW + tcol];
            ulonglong2 v2 = *(const ulonglong2*)&Vs[(k4 * 4 + 2) * AROW + tcol];
            ulonglong2 v3 = *(const ulonglong2*)&Vs[(k4 * 4 + 3) * AROW + tcol];
            ull t;
            t = pk2(p0.x, p0.x); fma2(o2[0][0], t, v0.x); fma2(o2[0][1], t, v0.y);
            t = pk2(p0.y, p0.y); fma2(o2[0][0], t, v1.x); fma2(o2[0][1], t, v1.y);
            t = pk2(p0.z, p0.z); fma2(o2[0][0], t, v2.x); fma2(o2[0][1], t, v2.y);
            t = pk2(p0.w, p0.w); fma2(o2[0][0], t, v3.x); fma2(o2[0][1], t, v3.y);
            t = pk2(p1.x, p1.x); fma2(o2[1][0], t, v0.x); fma2(o2[1][1], t, v0.y);
            t = pk2(p1.y, p1.y); fma2(o2[1][0], t, v1.x); fma2(o2[1][1], t, v1.y);
            t = pk2(p1.z, p1.z); fma2(o2[1][0], t, v2.x); fma2(o2[1][1], t, v2.y);
            t = pk2(p1.w, p1.w); fma2(o2[1][0], t, v3.x); fma2(o2[1][1], t, v3.y);
            t = pk2(p2.x, p2.x); fma2(o2[2][0], t, v0.x); fma2(o2[2][1], t, v0.y);
            t = pk2(p2.y, p2.y); fma2(o2[2][0], t, v1.x); fma2(o2[2][1], t, v1.y);
            t = pk2(p2.z, p2.z); fma2(o2[2][0], t, v2.x); fma2(o2[2][1], t, v2.y);
            t = pk2(p2.w, p2.w); fma2(o2[2][0], t, v3.x); fma2(o2[2][1], t, v3.y);
            t = pk2(p3.x, p3.x); fma2(o2[3][0], t, v0.x); fma2(o2[3][1], t, v0.y);
            t = pk2(p3.y, p3.y); fma2(o2[3][0], t, v1.x); fma2(o2[3][1], t, v1.y);
            t = pk2(p3.z, p3.z); fma2(o2[3][0], t, v2.x); fma2(o2[3][1], t, v2.y);
            t = pk2(p3.w, p3.w); fma2(o2[3][0], t, v3.x); fma2(o2[3][1], t, v3.y);
        }
        __syncthreads();
    }

    float* op = out + ((size_t)b * Tt + q0) * Hh;
#pragma unroll
    for (int i = 0; i < 4; i++) {
        float inv = (l[i] > 0.f) ? (1.f / l[i]) : 0.f;
        float o0, o1, o2f, o3;
        upk2(o2[i][0], o0, o1);
        upk2(o2[i][1], o2f, o3);
        float4 v = make_float4(o0 * inv, o1 * inv, o2f * inv, o3 * inv);
        *(float4*)(op + (size_t)(trow + i) * Hh + tcol) = v;
    }
}

// ---------------------------------------------------------------------------
extern "C" void kernel_launch(void* const* d_in, const int* in_sizes, int n_in,
                              void* d_out, int out_size)
{
    const float* x  = (const float*)d_in[0];
    const float* am = (const float*)d_in[1];
    const float* Wq = (const float*)d_in[2];
    const float* Wk = (const float*)d_in[3];
    const float* Wv = (const float*)d_in[4];
    float*       out = (float*)d_out;

    wtrans<<<(192 * Cc) / 256, 256>>>(Wq, Wk, Wv);

    cudaFuncSetAttribute(qkv_h,
                         cudaFuncAttributeMaxDynamicSharedMemorySize, QKV_SMEM);
    qkv_h<<<M_TOT / 128, 256, QKV_SMEM>>>(x);

    cudaFuncSetAttribute(attn_kernel,
                         cudaFuncAttributeMaxDynamicSharedMemorySize, ATTN_SMEM);
    dim3 g2(Tt / 64, Bb);
    attn_kernel<<<g2, 256, ATTN_SMEM>>>(am, out);
}

// round 7
// speedup vs baseline: 3.0841x; 2.2841x over previous
#include <cuda_runtime.h>
#include <cuda_fp16.h>
#include <math.h>
#include <stdint.h>

#define Bb 8
#define Tt 2048
#define Cc 768
#define Hh 64
#define M_TOT (Bb*Tt)

// scratch
__device__ float g_q[M_TOT*Hh];
__device__ float g_k[M_TOT*Hh];
__device__ float g_v[M_TOT*Hh];
__device__ float g_wt[192*Cc];   // fused transposed weights [n][k]

// ---------------------------------------------------------------------------
// helpers
// ---------------------------------------------------------------------------
__device__ __forceinline__ void mma_fp16(float* d, const uint32_t* a,
                                         uint32_t b0, uint32_t b1) {
    asm volatile(
        "mma.sync.aligned.m16n8k16.row.col.f32.f16.f16.f32 "
        "{%0,%1,%2,%3}, {%4,%5,%6,%7}, {%8,%9}, {%0,%1,%2,%3};"
        : "+f"(d[0]), "+f"(d[1]), "+f"(d[2]), "+f"(d[3])
        : "r"(a[0]), "r"(a[1]), "r"(a[2]), "r"(a[3]), "r"(b0), "r"(b1));
}

__device__ __forceinline__ uint32_t h2pack(float x, float y) {
    __half2 h = __floats2half2_rn(x, y);
    return *(uint32_t*)&h;
}

// split a float4 into hi/lo half2 pairs
__device__ __forceinline__ void cvt4(float4 v, uint32_t& h01, uint32_t& h23,
                                     uint32_t& l01, uint32_t& l23) {
    __half2 h0 = __floats2half2_rn(v.x, v.y);
    __half2 h1 = __floats2half2_rn(v.z, v.w);
    float lx = v.x - __half2float(__low2half(h0));
    float ly = v.y - __half2float(__high2half(h0));
    float lz = v.z - __half2float(__low2half(h1));
    float lw = v.w - __half2float(__high2half(h1));
    __half2 l0 = __floats2half2_rn(lx, ly);
    __half2 l1 = __floats2half2_rn(lz, lw);
    h01 = *(uint32_t*)&h0; h23 = *(uint32_t*)&h1;
    l01 = *(uint32_t*)&l0; l23 = *(uint32_t*)&l1;
}

// ---------------------------------------------------------------------------
// Kernel 0: transpose+fuse weights into g_wt[n][k]
// ---------------------------------------------------------------------------
__global__ void wtrans(const float* __restrict__ Wq,
                       const float* __restrict__ Wk,
                       const float* __restrict__ Wv)
{
    int idx = blockIdx.x * 256 + threadIdx.x;
    int n = idx / Cc, k = idx % Cc;
    const float* W = (n < 64) ? Wq : (n < 128 ? Wk : Wv);
    g_wt[idx] = W[(size_t)k * Hh + (n & 63)];
}

// ---------------------------------------------------------------------------
// Kernel 1: QKV projection via split-fp16 mma.sync (unchanged from R6).
// ---------------------------------------------------------------------------
#define BKh 32
#define NCH (Cc / BKh)
#define W_AH 0
#define W_AL 5120
#define W_BH 10240
#define W_BL 17920
#define QKV_SMEM (25600 * 4)

__global__ __launch_bounds__(256) void qkv_h(const float* __restrict__ x)
{
    extern __shared__ uint32_t smw[];

    const int tid  = threadIdx.x;
    const int lane = tid & 31, wid = tid >> 5;
    const int m0   = blockIdx.x * 128;
    const int g    = lane >> 2, tig = lane & 3;
    const int wm   = wid & 3,  wn  = wid >> 2;

    int rowA[4], cA[4], rowB[6], cB[6];
#pragma unroll
    for (int r = 0; r < 4; r++) { int idx = r*256+tid; rowA[r]=idx>>3; cA[r]=(idx&7)<<2; }
#pragma unroll
    for (int r = 0; r < 6; r++) { int idx = r*256+tid; rowB[r]=idx>>3; cB[r]=(idx&7)<<2; }

    float acc[2][12][4];
#pragma unroll
    for (int i = 0; i < 2; i++)
#pragma unroll
        for (int j = 0; j < 12; j++)
#pragma unroll
            for (int r = 0; r < 4; r++) acc[i][j][r] = 0.f;

#pragma unroll
    for (int r = 0; r < 4; r++) {
        float4 v = *(const float4*)(x + (size_t)(m0 + rowA[r]) * Cc + cA[r]);
        uint32_t h01, h23, l01, l23; cvt4(v, h01, h23, l01, l23);
        int wi = rowA[r] * 20 + (cA[r] >> 1);
        *(uint2*)&smw[W_AH + wi] = make_uint2(h01, h23);
        *(uint2*)&smw[W_AL + wi] = make_uint2(l01, l23);
    }
#pragma unroll
    for (int r = 0; r < 6; r++) {
        float4 v = *(const float4*)(g_wt + (size_t)rowB[r] * Cc + cB[r]);
        uint32_t h01, h23, l01, l23; cvt4(v, h01, h23, l01, l23);
        int wi = rowB[r] * 20 + (cB[r] >> 1);
        *(uint2*)&smw[W_BH + wi] = make_uint2(h01, h23);
        *(uint2*)&smw[W_BL + wi] = make_uint2(l01, l23);
    }
    __syncthreads();

    for (int t = 0; t < NCH; t++) {
        const int buf = t & 1;
        float4 stA[4], stB[6];
        if (t + 1 < NCH) {
            const int k0 = (t + 1) * BKh;
#pragma unroll
            for (int r = 0; r < 4; r++)
                stA[r] = *(const float4*)(x + (size_t)(m0 + rowA[r]) * Cc + k0 + cA[r]);
#pragma unroll
            for (int r = 0; r < 6; r++)
                stB[r] = *(const float4*)(g_wt + (size_t)rowB[r] * Cc + k0 + cB[r]);
        }

        const uint32_t* Ah = smw + W_AH + buf * 2560;
        const uint32_t* Al = smw + W_AL + buf * 2560;
        const uint32_t* Bh = smw + W_BH + buf * 3840;
        const uint32_t* Bl = smw + W_BL + buf * 3840;

#pragma unroll
        for (int kk2 = 0; kk2 < 16; kk2 += 8) {
            uint32_t ah[2][4], al[2][4];
#pragma unroll
            for (int i = 0; i < 2; i++) {
                int r0 = (wm * 32 + i * 16 + g) * 20 + kk2 + tig;
                ah[i][0] = Ah[r0];        ah[i][1] = Ah[r0 + 160];
                ah[i][2] = Ah[r0 + 4];    ah[i][3] = Ah[r0 + 164];
                al[i][0] = Al[r0];        al[i][1] = Al[r0 + 160];
                al[i][2] = Al[r0 + 4];    al[i][3] = Al[r0 + 164];
            }
#pragma unroll
            for (int j = 0; j < 12; j++) {
                int nb = (wn * 96 + j * 8 + g) * 20 + kk2 + tig;
                uint32_t bh0 = Bh[nb], bh1 = Bh[nb + 4];
                uint32_t bl0 = Bl[nb], bl1 = Bl[nb + 4];
                mma_fp16(acc[0][j], ah[0], bh0, bh1);
                mma_fp16(acc[1][j], ah[1], bh0, bh1);
                mma_fp16(acc[0][j], ah[0], bl0, bl1);
                mma_fp16(acc[1][j], ah[1], bl0, bl1);
                mma_fp16(acc[0][j], al[0], bh0, bh1);
                mma_fp16(acc[1][j], al[1], bh0, bh1);
            }
        }

        if (t + 1 < NCH) {
            uint32_t* Ahd = smw + W_AH + (buf ^ 1) * 2560;
            uint32_t* Ald = smw + W_AL + (buf ^ 1) * 2560;
            uint32_t* Bhd = smw + W_BH + (buf ^ 1) * 3840;
            uint32_t* Bld = smw + W_BL + (buf ^ 1) * 3840;
#pragma unroll
            for (int r = 0; r < 4; r++) {
                uint32_t h01, h23, l01, l23; cvt4(stA[r], h01, h23, l01, l23);
                int wi = rowA[r] * 20 + (cA[r] >> 1);
                *(uint2*)&Ahd[wi] = make_uint2(h01, h23);
                *(uint2*)&Ald[wi] = make_uint2(l01, l23);
            }
#pragma unroll
            for (int r = 0; r < 6; r++) {
                uint32_t h01, h23, l01, l23; cvt4(stB[r], h01, h23, l01, l23);
                int wi = rowB[r] * 20 + (cB[r] >> 1);
                *(uint2*)&Bhd[wi] = make_uint2(h01, h23);
                *(uint2*)&Bld[wi] = make_uint2(l01, l23);
            }
        }
        __syncthreads();
    }

#pragma unroll
    for (int i = 0; i < 2; i++) {
        int r0 = m0 + wm * 32 + i * 16 + g;
#pragma unroll
        for (int j = 0; j < 12; j++) {
            int c = wn * 96 + j * 8 + tig * 2;
            float* op = (c < 64) ? g_q : (c < 128 ? g_k : g_v);
            int oc = c & 63;
            *(float2*)(op + (size_t)r0 * Hh + oc) =
                make_float2(acc[i][j][0], acc[i][j][1]);
            *(float2*)(op + (size_t)(r0 + 8) * Hh + oc) =
                make_float2(acc[i][j][2], acc[i][j][3]);
        }
    }
}

// ---------------------------------------------------------------------------
// Kernel 2: causal flash attention via fp16 mma.sync (FA2 warp layout).
// CTA = 128 query rows; 8 warps x m16, full N; K/V tiles of 64.
// Q,K fp16; V split hi/lo fp16 (2-pass PV). P stays in registers
// (S C-frags map directly onto PV A-frags).
// Smem rows = 36 u32 words: fragment LDS banks = 4g+t, conflict-free.
// ---------------------------------------------------------------------------
#define OQ  0                      // 128*36
#define OK_ 4608                   // 64*36
#define OVH 6912
#define OVL 9216
#define OAM 11520                  // 128 floats
#define ATTN_SMEM ((11520 + 128) * 4)

__global__ __launch_bounds__(256) void attn_mma(
    const float* __restrict__ amask,
    float* __restrict__ out)
{
    extern __shared__ uint32_t smw[];
    uint32_t* Qs  = smw + OQ;
    uint32_t* Ks  = smw + OK_;
    uint32_t* VH  = smw + OVH;
    uint32_t* VL  = smw + OVL;
    float*    ams = (float*)(smw + OAM);

    const int b   = blockIdx.y;
    const int q0  = blockIdx.x * 128;
    const int tid = threadIdx.x;
    const int lane = tid & 31, w = tid >> 5;
    const int g = lane >> 2, t = lane & 3;

    // stage Q tile (128 x 64) as fp16
    const float* qp = g_q + ((size_t)b * Tt + q0) * Hh;
#pragma unroll
    for (int r = 0; r < 8; r++) {
        int idx = r * 256 + tid;
        int row = idx >> 4, c4 = (idx & 15) << 2;
        float4 v = *(const float4*)(qp + row * Hh + c4);
        Qs[row * 36 + (c4 >> 1)]     = h2pack(v.x, v.y);
        Qs[row * 36 + (c4 >> 1) + 1] = h2pack(v.z, v.w);
    }
    if (tid < 128) ams[tid] = amask[(size_t)b * Tt + q0 + tid];

    // per-row online softmax state (rows w*16+g and w*16+g+8)
    float m0 = -INFINITY, m1 = -INFINITY, l0 = 0.f, l1 = 0.f;
    float o[8][4];
#pragma unroll
    for (int f = 0; f < 8; f++)
#pragma unroll
        for (int r = 0; r < 4; r++) o[f][r] = 0.f;

    const float am0 = amask[(size_t)b * Tt + q0 + w * 16 + g];
    const float am1 = amask[(size_t)b * Tt + q0 + w * 16 + g + 8];
    const int qg0 = q0 + w * 16 + g;
    const int qg1 = qg0 + 8;

    __syncthreads();

    const int jend = q0 + 64;
    for (int j0 = 0; j0 <= jend; j0 += 64) {
        // stage K (64x64 -> [j][h] fp16) and V transposed split ([h][j])
        const float* kp = g_k + ((size_t)b * Tt + j0) * Hh;
        const float* vp = g_v + ((size_t)b * Tt + j0) * Hh;
#pragma unroll
        for (int r = 0; r < 4; r++) {
            int idx = r * 256 + tid;
            int j = idx >> 4, c4 = (idx & 15) << 2;
            float4 kv = *(const float4*)(kp + j * Hh + c4);
            Ks[j * 36 + (c4 >> 1)]     = h2pack(kv.x, kv.y);
            Ks[j * 36 + (c4 >> 1) + 1] = h2pack(kv.z, kv.w);
        }
#pragma unroll
        for (int r = 0; r < 2; r++) {
            int idx = r * 256 + tid;
            int jp = idx & 31, h4 = (idx >> 5) << 2;
            int j = jp * 2;
            float4 v0 = *(const float4*)(vp + j * Hh + h4);
            float4 v1 = *(const float4*)(vp + (j + 1) * Hh + h4);
            float e0[4] = {v0.x, v0.y, v0.z, v0.w};
            float e1[4] = {v1.x, v1.y, v1.z, v1.w};
#pragma unroll
            for (int i = 0; i < 4; i++) {
                __half a0 = __float2half_rn(e0[i]);
                __half a1 = __float2half_rn(e1[i]);
                float r0f = e0[i] - __half2float(a0);
                float r1f = e1[i] - __half2float(a1);
                __half2 hh = __halves2half2(a0, a1);
                VH[(h4 + i) * 36 + jp] = *(uint32_t*)&hh;
                VL[(h4 + i) * 36 + jp] = h2pack(r0f, r1f);
            }
        }
        __syncthreads();

        // S = Q K^T : 8 n-frags x 4 k-steps
        float c[8][4];
#pragma unroll
        for (int f = 0; f < 8; f++)
#pragma unroll
            for (int r = 0; r < 4; r++) c[f][r] = 0.f;
#pragma unroll
        for (int ks = 0; ks < 4; ks++) {
            uint32_t a[4];
            int base = (w * 16 + g) * 36 + ks * 8 + t;
            a[0] = Qs[base];
            a[1] = Qs[base + 8 * 36];
            a[2] = Qs[base + 4];
            a[3] = Qs[base + 8 * 36 + 4];
#pragma unroll
            for (int f = 0; f < 8; f++) {
                int nb = (f * 8 + g) * 36 + ks * 8 + t;
                mma_fp16(c[f], a, Ks[nb], Ks[nb + 4]);
            }
        }

        // masks: am * (s/8) ; ==0 -> -inf ; causal -> -inf
        float mx0 = -INFINITY, mx1 = -INFINITY;
#pragma unroll
        for (int f = 0; f < 8; f++) {
            int col = j0 + f * 8 + t * 2;
            float v0 = c[f][0] * 0.125f * am0;
            float v1 = c[f][1] * 0.125f * am0;
            float v2 = c[f][2] * 0.125f * am1;
            float v3 = c[f][3] * 0.125f * am1;
            if (v0 == 0.f || col     > qg0) v0 = -INFINITY;
            if (v1 == 0.f || col + 1 > qg0) v1 = -INFINITY;
            if (v2 == 0.f || col     > qg1) v2 = -INFINITY;
            if (v3 == 0.f || col + 1 > qg1) v3 = -INFINITY;
            c[f][0] = v0; c[f][1] = v1; c[f][2] = v2; c[f][3] = v3;
            mx0 = fmaxf(mx0, fmaxf(v0, v1));
            mx1 = fmaxf(mx1, fmaxf(v2, v3));
        }
        mx0 = fmaxf(mx0, __shfl_xor_sync(0xffffffffu, mx0, 1));
        mx0 = fmaxf(mx0, __shfl_xor_sync(0xffffffffu, mx0, 2));
        mx1 = fmaxf(mx1, __shfl_xor_sync(0xffffffffu, mx1, 1));
        mx1 = fmaxf(mx1, __shfl_xor_sync(0xffffffffu, mx1, 2));

        float mn0 = fmaxf(m0, mx0), mn1 = fmaxf(m1, mx1);
        float alpha0, alpha1, ls0 = 0.f, ls1 = 0.f;
        uint32_t p01[8], p23[8];
        if (mn0 == -INFINITY) {
            alpha0 = 1.f;
#pragma unroll
            for (int f = 0; f < 8; f++) { c[f][0] = 0.f; c[f][1] = 0.f; }
        } else {
            alpha0 = __expf(m0 - mn0);
#pragma unroll
            for (int f = 0; f < 8; f++) {
                c[f][0] = __expf(c[f][0] - mn0);
                c[f][1] = __expf(c[f][1] - mn0);
                ls0 += c[f][0] + c[f][1];
            }
        }
        if (mn1 == -INFINITY) {
            alpha1 = 1.f;
#pragma unroll
            for (int f = 0; f < 8; f++) { c[f][2] = 0.f; c[f][3] = 0.f; }
        } else {
            alpha1 = __expf(m1 - mn1);
#pragma unroll
            for (int f = 0; f < 8; f++) {
                c[f][2] = __expf(c[f][2] - mn1);
                c[f][3] = __expf(c[f][3] - mn1);
                ls1 += c[f][2] + c[f][3];
            }
        }
        m0 = mn0; m1 = mn1;
        ls0 += __shfl_xor_sync(0xffffffffu, ls0, 1);
        ls0 += __shfl_xor_sync(0xffffffffu, ls0, 2);
        ls1 += __shfl_xor_sync(0xffffffffu, ls1, 1);
        ls1 += __shfl_xor_sync(0xffffffffu, ls1, 2);
        l0 = l0 * alpha0 + ls0;
        l1 = l1 * alpha1 + ls1;

#pragma unroll
        for (int f = 0; f < 8; f++) {
            p01[f] = h2pack(c[f][0], c[f][1]);
            p23[f] = h2pack(c[f][2], c[f][3]);
            o[f][0] *= alpha0; o[f][1] *= alpha0;
            o[f][2] *= alpha1; o[f][3] *= alpha1;
        }

        // O += P V  (2 passes: V hi + V lo)
#pragma unroll
        for (int s = 0; s < 4; s++) {
            uint32_t a[4];
            a[0] = p01[2 * s];     a[1] = p23[2 * s];
            a[2] = p01[2 * s + 1]; a[3] = p23[2 * s + 1];
#pragma unroll
            for (int f = 0; f < 8; f++) {
                int nb = (f * 8 + g) * 36 + s * 8 + t;
                mma_fp16(o[f], a, VH[nb], VH[nb + 4]);
                mma_fp16(o[f], a, VL[nb], VL[nb + 4]);
            }
        }
        __syncthreads();
    }

    // epilogue: O / l
    float inv0 = (l0 > 0.f) ? (1.f / l0) : 0.f;
    float inv1 = (l1 > 0.f) ? (1.f / l1) : 0.f;
    float* op0 = out + ((size_t)b * Tt + qg0) * Hh;
    float* op1 = out + ((size_t)b * Tt + qg1) * Hh;
#pragma unroll
    for (int f = 0; f < 8; f++) {
        int col = f * 8 + t * 2;
        *(float2*)(op0 + col) = make_float2(o[f][0] * inv0, o[f][1] * inv0);
        *(float2*)(op1 + col) = make_float2(o[f][2] * inv1, o[f][3] * inv1);
    }
}

// ---------------------------------------------------------------------------
extern "C" void kernel_launch(void* const* d_in, const int* in_sizes, int n_in,
                              void* d_out, int out_size)
{
    const float* x  = (const float*)d_in[0];
    const float* am = (const float*)d_in[1];
    const float* Wq = (const float*)d_in[2];
    const float* Wk = (const float*)d_in[3];
    const float* Wv = (const float*)d_in[4];
    float*       out = (float*)d_out;

    wtrans<<<(192 * Cc) / 256, 256>>>(Wq, Wk, Wv);

    cudaFuncSetAttribute(qkv_h,
                         cudaFuncAttributeMaxDynamicSharedMemorySize, QKV_SMEM);
    qkv_h<<<M_TOT / 128, 256, QKV_SMEM>>>(x);

    cudaFuncSetAttribute(attn_mma,
                         cudaFuncAttributeMaxDynamicSharedMemorySize, ATTN_SMEM);
    dim3 g2(Tt / 128, Bb);
    attn_mma<<<g2, 256, ATTN_SMEM>>>(am, out);
}

// round 8
// speedup vs baseline: 3.7335x; 1.2106x over previous
#include <cuda_runtime.h>
#include <cuda_fp16.h>
#include <math.h>
#include <stdint.h>

#define Bb 8
#define Tt 2048
#define Cc 768
#define Hh 64
#define M_TOT (Bb*Tt)

// scratch
__device__ float g_q[M_TOT*Hh];
__device__ float g_k[M_TOT*Hh];
__device__ float g_v[M_TOT*Hh];
__device__ float g_wt[192*Cc];   // fused transposed weights [n][k]

// ---------------------------------------------------------------------------
// helpers
// ---------------------------------------------------------------------------
__device__ __forceinline__ void mma_fp16(float* d, const uint32_t* a,
                                         uint32_t b0, uint32_t b1) {
    asm volatile(
        "mma.sync.aligned.m16n8k16.row.col.f32.f16.f16.f32 "
        "{%0,%1,%2,%3}, {%4,%5,%6,%7}, {%8,%9}, {%0,%1,%2,%3};"
        : "+f"(d[0]), "+f"(d[1]), "+f"(d[2]), "+f"(d[3])
        : "r"(a[0]), "r"(a[1]), "r"(a[2]), "r"(a[3]), "r"(b0), "r"(b1));
}

__device__ __forceinline__ void ldsm_x4(uint32_t& d0, uint32_t& d1,
                                        uint32_t& d2, uint32_t& d3,
                                        uint32_t saddr) {
    asm volatile("ldmatrix.sync.aligned.m8n8.x4.shared.b16 {%0,%1,%2,%3}, [%4];"
                 : "=r"(d0), "=r"(d1), "=r"(d2), "=r"(d3) : "r"(saddr));
}

__device__ __forceinline__ uint32_t smem_u32(const void* p) {
    uint32_t a;
    asm("{ .reg .u64 t; cvta.to.shared.u64 t, %1; cvt.u32.u64 %0, t; }"
        : "=r"(a) : "l"(p));
    return a;
}

__device__ __forceinline__ uint32_t h2pack(float x, float y) {
    __half2 h = __floats2half2_rn(x, y);
    return *(uint32_t*)&h;
}

// ---------------------------------------------------------------------------
// Kernel 0: transpose+fuse weights into g_wt[n][k]
// ---------------------------------------------------------------------------
__global__ void wtrans(const float* __restrict__ Wq,
                       const float* __restrict__ Wk,
                       const float* __restrict__ Wv)
{
    int idx = blockIdx.x * 256 + threadIdx.x;
    int n = idx / Cc, k = idx % Cc;
    const float* W = (n < 64) ? Wq : (n < 128 ? Wk : Wv);
    g_wt[idx] = W[(size_t)k * Hh + (n & 63)];
}

// ---------------------------------------------------------------------------
// Kernel 1: QKV projection, 1-pass fp16 mma.sync + ldmatrix.
// CTA tile 128(M) x 192(N fused), BK=32, double-buffered fp16 smem.
// Rows padded to 40 fp16 (20 words) -> ldmatrix phases conflict-free.
// 8 warps as 4(M)x2(N): warp tile 32x96 = 2 x 12 m16n8k16 fragments.
// ---------------------------------------------------------------------------
#define BKh 32
#define NCH (Cc / BKh)         // 24
#define W_A 0                  // [2][128*20] words
#define W_B 5120               // [2][192*20] words
#define QKV_SMEM (12800 * 4)   // 51200 B

__global__ __launch_bounds__(256) void qkv_h(const float* __restrict__ x)
{
    extern __shared__ uint32_t smw[];
    const uint32_t sb = smem_u32(smw);

    const int tid  = threadIdx.x;
    const int lane = tid & 31, wid = tid >> 5;
    const int m0   = blockIdx.x * 128;
    const int g    = lane >> 2, tig = lane & 3;
    const int wm   = wid & 3,  wn  = wid >> 2;

    // load mappings (per chunk): A 4 float4/thread, B 6 float4/thread
    int rowA[4], cA[4], rowB[6], cB[6];
#pragma unroll
    for (int r = 0; r < 4; r++) { int idx = r*256+tid; rowA[r]=idx>>3; cA[r]=(idx&7)<<2; }
#pragma unroll
    for (int r = 0; r < 6; r++) { int idx = r*256+tid; rowB[r]=idx>>3; cB[r]=(idx&7)<<2; }

    // ldmatrix lane-derived offsets
    const int a_lrow = wm * 32 + (lane & 15);          // + i*16
    const int a_kh   = ((lane >> 4) & 1) << 2;         // k-half word
    const int b_lrow = wn * 96 + ((lane >> 4) & 1) * 8 + (lane & 7);  // + p*16
    const int b_kh   = ((lane >> 3) & 1) << 2;

    float acc[2][12][4];
#pragma unroll
    for (int i = 0; i < 2; i++)
#pragma unroll
        for (int j = 0; j < 12; j++)
#pragma unroll
            for (int r = 0; r < 4; r++) acc[i][j][r] = 0.f;

    // prologue: chunk 0 -> buffer 0 (hi halves only)
#pragma unroll
    for (int r = 0; r < 4; r++) {
        float4 v = *(const float4*)(x + (size_t)(m0 + rowA[r]) * Cc + cA[r]);
        int wi = rowA[r] * 20 + (cA[r] >> 1);
        *(uint2*)&smw[W_A + wi] = make_uint2(h2pack(v.x, v.y), h2pack(v.z, v.w));
    }
#pragma unroll
    for (int r = 0; r < 6; r++) {
        float4 v = *(const float4*)(g_wt + (size_t)rowB[r] * Cc + cB[r]);
        int wi = rowB[r] * 20 + (cB[r] >> 1);
        *(uint2*)&smw[W_B + wi] = make_uint2(h2pack(v.x, v.y), h2pack(v.z, v.w));
    }
    __syncthreads();

    for (int t = 0; t < NCH; t++) {
        const int buf = t & 1;
        float4 stA[4], stB[6];
        if (t + 1 < NCH) {
            const int k0 = (t + 1) * BKh;
#pragma unroll
            for (int r = 0; r < 4; r++)
                stA[r] = *(const float4*)(x + (size_t)(m0 + rowA[r]) * Cc + k0 + cA[r]);
#pragma unroll
            for (int r = 0; r < 6; r++)
                stB[r] = *(const float4*)(g_wt + (size_t)rowB[r] * Cc + k0 + cB[r]);
        }

        const uint32_t Abase = sb + (W_A + buf * 2560) * 4;
        const uint32_t Bbase = sb + (W_B + buf * 3840) * 4;

#pragma unroll
        for (int kk2 = 0; kk2 < 16; kk2 += 8) {
            uint32_t a[2][4];
#pragma unroll
            for (int i = 0; i < 2; i++)
                ldsm_x4(a[i][0], a[i][1], a[i][2], a[i][3],
                        Abase + (uint32_t)(((a_lrow + i * 16) * 20 + kk2 + a_kh) * 4));
            uint32_t bf[12][2];
#pragma unroll
            for (int p = 0; p < 6; p++) {
                uint32_t d0, d1, d2, d3;
                ldsm_x4(d0, d1, d2, d3,
                        Bbase + (uint32_t)(((b_lrow + p * 16) * 20 + kk2 + b_kh) * 4));
                bf[2*p][0] = d0; bf[2*p][1] = d1;
                bf[2*p+1][0] = d2; bf[2*p+1][1] = d3;
            }
#pragma unroll
            for (int j = 0; j < 12; j++) {
                mma_fp16(acc[0][j], a[0], bf[j][0], bf[j][1]);
                mma_fp16(acc[1][j], a[1], bf[j][0], bf[j][1]);
            }
        }

        if (t + 1 < NCH) {
            uint32_t* Ad = smw + W_A + (buf ^ 1) * 2560;
            uint32_t* Bd = smw + W_B + (buf ^ 1) * 3840;
#pragma unroll
            for (int r = 0; r < 4; r++) {
                int wi = rowA[r] * 20 + (cA[r] >> 1);
                *(uint2*)&Ad[wi] =
                    make_uint2(h2pack(stA[r].x, stA[r].y), h2pack(stA[r].z, stA[r].w));
            }
#pragma unroll
            for (int r = 0; r < 6; r++) {
                int wi = rowB[r] * 20 + (cB[r] >> 1);
                *(uint2*)&Bd[wi] =
                    make_uint2(h2pack(stB[r].x, stB[r].y), h2pack(stB[r].z, stB[r].w));
            }
        }
        __syncthreads();
    }

    // epilogue
#pragma unroll
    for (int i = 0; i < 2; i++) {
        int r0 = m0 + wm * 32 + i * 16 + g;
#pragma unroll
        for (int j = 0; j < 12; j++) {
            int c = wn * 96 + j * 8 + tig * 2;
            float* op = (c < 64) ? g_q : (c < 128 ? g_k : g_v);
            int oc = c & 63;
            *(float2*)(op + (size_t)r0 * Hh + oc) =
                make_float2(acc[i][j][0], acc[i][j][1]);
            *(float2*)(op + (size_t)(r0 + 8) * Hh + oc) =
                make_float2(acc[i][j][2], acc[i][j][3]);
        }
    }
}

// ---------------------------------------------------------------------------
// Kernel 2: causal flash attention via fp16 mma.sync (unchanged from R7).
// ---------------------------------------------------------------------------
#define OQ  0
#define OK_ 4608
#define OVH 6912
#define OVL 9216
#define OAM 11520
#define ATTN_SMEM ((11520 + 128) * 4)

__global__ __launch_bounds__(256) void attn_mma(
    const float* __restrict__ amask,
    float* __restrict__ out)
{
    extern __shared__ uint32_t smw[];
    uint32_t* Qs  = smw + OQ;
    uint32_t* Ks  = smw + OK_;
    uint32_t* VH  = smw + OVH;
    uint32_t* VL  = smw + OVL;
    float*    ams = (float*)(smw + OAM);

    const int b   = blockIdx.y;
    const int q0  = blockIdx.x * 128;
    const int tid = threadIdx.x;
    const int lane = tid & 31, w = tid >> 5;
    const int g = lane >> 2, t = lane & 3;

    const float* qp = g_q + ((size_t)b * Tt + q0) * Hh;
#pragma unroll
    for (int r = 0; r < 8; r++) {
        int idx = r * 256 + tid;
        int row = idx >> 4, c4 = (idx & 15) << 2;
        float4 v = *(const float4*)(qp + row * Hh + c4);
        Qs[row * 36 + (c4 >> 1)]     = h2pack(v.x, v.y);
        Qs[row * 36 + (c4 >> 1) + 1] = h2pack(v.z, v.w);
    }
    if (tid < 128) ams[tid] = amask[(size_t)b * Tt + q0 + tid];

    float m0 = -INFINITY, m1 = -INFINITY, l0 = 0.f, l1 = 0.f;
    float o[8][4];
#pragma unroll
    for (int f = 0; f < 8; f++)
#pragma unroll
        for (int r = 0; r < 4; r++) o[f][r] = 0.f;

    const float am0 = amask[(size_t)b * Tt + q0 + w * 16 + g];
    const float am1 = amask[(size_t)b * Tt + q0 + w * 16 + g + 8];
    const int qg0 = q0 + w * 16 + g;
    const int qg1 = qg0 + 8;

    __syncthreads();

    const int jend = q0 + 64;
    for (int j0 = 0; j0 <= jend; j0 += 64) {
        const float* kp = g_k + ((size_t)b * Tt + j0) * Hh;
        const float* vp = g_v + ((size_t)b * Tt + j0) * Hh;
#pragma unroll
        for (int r = 0; r < 4; r++) {
            int idx = r * 256 + tid;
            int j = idx >> 4, c4 = (idx & 15) << 2;
            float4 kv = *(const float4*)(kp + j * Hh + c4);
            Ks[j * 36 + (c4 >> 1)]     = h2pack(kv.x, kv.y);
            Ks[j * 36 + (c4 >> 1) + 1] = h2pack(kv.z, kv.w);
        }
#pragma unroll
        for (int r = 0; r < 2; r++) {
            int idx = r * 256 + tid;
            int jp = idx & 31, h4 = (idx >> 5) << 2;
            int j = jp * 2;
            float4 v0 = *(const float4*)(vp + j * Hh + h4);
            float4 v1 = *(const float4*)(vp + (j + 1) * Hh + h4);
            float e0[4] = {v0.x, v0.y, v0.z, v0.w};
            float e1[4] = {v1.x, v1.y, v1.z, v1.w};
#pragma unroll
            for (int i = 0; i < 4; i++) {
                __half a0 = __float2half_rn(e0[i]);
                __half a1 = __float2half_rn(e1[i]);
                float r0f = e0[i] - __half2float(a0);
                float r1f = e1[i] - __half2float(a1);
                __half2 hh = __halves2half2(a0, a1);
                VH[(h4 + i) * 36 + jp] = *(uint32_t*)&hh;
                VL[(h4 + i) * 36 + jp] = h2pack(r0f, r1f);
            }
        }
        __syncthreads();

        float c[8][4];
#pragma unroll
        for (int f = 0; f < 8; f++)
#pragma unroll
            for (int r = 0; r < 4; r++) c[f][r] = 0.f;
#pragma unroll
        for (int ks = 0; ks < 4; ks++) {
            uint32_t a[4];
            int base = (w * 16 + g) * 36 + ks * 8 + t;
            a[0] = Qs[base];
            a[1] = Qs[base + 8 * 36];
            a[2] = Qs[base + 4];
            a[3] = Qs[base + 8 * 36 + 4];
#pragma unroll
            for (int f = 0; f < 8; f++) {
                int nb = (f * 8 + g) * 36 + ks * 8 + t;
                mma_fp16(c[f], a, Ks[nb], Ks[nb + 4]);
            }
        }

        float mx0 = -INFINITY, mx1 = -INFINITY;
#pragma unroll
        for (int f = 0; f < 8; f++) {
            int col = j0 + f * 8 + t * 2;
            float v0 = c[f][0] * 0.125f * am0;
            float v1 = c[f][1] * 0.125f * am0;
            float v2 = c[f][2] * 0.125f * am1;
            float v3 = c[f][3] * 0.125f * am1;
            if (v0 == 0.f || col     > qg0) v0 = -INFINITY;
            if (v1 == 0.f || col + 1 > qg0) v1 = -INFINITY;
            if (v2 == 0.f || col     > qg1) v2 = -INFINITY;
            if (v3 == 0.f || col + 1 > qg1) v3 = -INFINITY;
            c[f][0] = v0; c[f][1] = v1; c[f][2] = v2; c[f][3] = v3;
            mx0 = fmaxf(mx0, fmaxf(v0, v1));
            mx1 = fmaxf(mx1, fmaxf(v2, v3));
        }
        mx0 = fmaxf(mx0, __shfl_xor_sync(0xffffffffu, mx0, 1));
        mx0 = fmaxf(mx0, __shfl_xor_sync(0xffffffffu, mx0, 2));
        mx1 = fmaxf(mx1, __shfl_xor_sync(0xffffffffu, mx1, 1));
        mx1 = fmaxf(mx1, __shfl_xor_sync(0xffffffffu, mx1, 2));

        float mn0 = fmaxf(m0, mx0), mn1 = fmaxf(m1, mx1);
        float alpha0, alpha1, ls0 = 0.f, ls1 = 0.f;
        uint32_t p01[8], p23[8];
        if (mn0 == -INFINITY) {
            alpha0 = 1.f;
#pragma unroll
            for (int f = 0; f < 8; f++) { c[f][0] = 0.f; c[f][1] = 0.f; }
        } else {
            alpha0 = __expf(m0 - mn0);
#pragma unroll
            for (int f = 0; f < 8; f++) {
                c[f][0] = __expf(c[f][0] - mn0);
                c[f][1] = __expf(c[f][1] - mn0);
                ls0 += c[f][0] + c[f][1];
            }
        }
        if (mn1 == -INFINITY) {
            alpha1 = 1.f;
#pragma unroll
            for (int f = 0; f < 8; f++) { c[f][2] = 0.f; c[f][3] = 0.f; }
        } else {
            alpha1 = __expf(m1 - mn1);
#pragma unroll
            for (int f = 0; f < 8; f++) {
                c[f][2] = __expf(c[f][2] - mn1);
                c[f][3] = __expf(c[f][3] - mn1);
                ls1 += c[f][2] + c[f][3];
            }
        }
        m0 = mn0; m1 = mn1;
        ls0 += __shfl_xor_sync(0xffffffffu, ls0, 1);
        ls0 += __shfl_xor_sync(0xffffffffu, ls0, 2);
        ls1 += __shfl_xor_sync(0xffffffffu, ls1, 1);
        ls1 += __shfl_xor_sync(0xffffffffu, ls1, 2);
        l0 = l0 * alpha0 + ls0;
        l1 = l1 * alpha1 + ls1;

#pragma unroll
        for (int f = 0; f < 8; f++) {
            p01[f] = h2pack(c[f][0], c[f][1]);
            p23[f] = h2pack(c[f][2], c[f][3]);
            o[f][0] *= alpha0; o[f][1] *= alpha0;
            o[f][2] *= alpha1; o[f][3] *= alpha1;
        }

#pragma unroll
        for (int s = 0; s < 4; s++) {
            uint32_t a[4];
            a[0] = p01[2 * s];     a[1] = p23[2 * s];
            a[2] = p01[2 * s + 1]; a[3] = p23[2 * s + 1];
#pragma unroll
            for (int f = 0; f < 8; f++) {
                int nb = (f * 8 + g) * 36 + s * 8 + t;
                mma_fp16(o[f], a, VH[nb], VH[nb + 4]);
                mma_fp16(o[f], a, VL[nb], VL[nb + 4]);
            }
        }
        __syncthreads();
    }

    float inv0 = (l0 > 0.f) ? (1.f / l0) : 0.f;
    float inv1 = (l1 > 0.f) ? (1.f / l1) : 0.f;
    float* op0 = out + ((size_t)b * Tt + qg0) * Hh;
    float* op1 = out + ((size_t)b * Tt + qg1) * Hh;
#pragma unroll
    for (int f = 0; f < 8; f++) {
        int col = f * 8 + t * 2;
        *(float2*)(op0 + col) = make_float2(o[f][0] * inv0, o[f][1] * inv0);
        *(float2*)(op1 + col) = make_float2(o[f][2] * inv1, o[f][3] * inv1);
    }
}

// ---------------------------------------------------------------------------
extern "C" void kernel_launch(void* const* d_in, const int* in_sizes, int n_in,
                              void* d_out, int out_size)
{
    const float* x  = (const float*)d_in[0];
    const float* am = (const float*)d_in[1];
    const float* Wq = (const float*)d_in[2];
    const float* Wk = (const float*)d_in[3];
    const float* Wv = (const float*)d_in[4];
    float*       out = (float*)d_out;

    wtrans<<<(192 * Cc) / 256, 256>>>(Wq, Wk, Wv);

    cudaFuncSetAttribute(qkv_h,
                         cudaFuncAttributeMaxDynamicSharedMemorySize, QKV_SMEM);
    qkv_h<<<M_TOT / 128, 256, QKV_SMEM>>>(x);

    cudaFuncSetAttribute(attn_mma,
                         cudaFuncAttributeMaxDynamicSharedMemorySize, ATTN_SMEM);
    dim3 g2(Tt / 128, Bb);
    attn_mma<<<g2, 256, ATTN_SMEM>>>(am, out);
}

// round 9
// speedup vs baseline: 4.6735x; 1.2518x over previous
#include <cuda_runtime.h>
#include <cuda_fp16.h>
#include <math.h>
#include <stdint.h>

#define Bb 8
#define Tt 2048
#define Cc 768
#define Hh 64
#define M_TOT (Bb*Tt)

// fp16 scratch (half2 packed in uint32)
__device__ uint32_t g_xh[M_TOT*Cc/2];    // x as fp16 [row][k]
__device__ uint32_t g_wth[192*Cc/2];     // fused transposed weights fp16 [n][k]
__device__ uint32_t g_qh[M_TOT*32];      // q fp16 [row][h]
__device__ uint32_t g_kh[M_TOT*32];
__device__ uint32_t g_vh[M_TOT*32];

// ---------------------------------------------------------------------------
// helpers
// ---------------------------------------------------------------------------
__device__ __forceinline__ void mma_fp16(float* d, const uint32_t* a,
                                         uint32_t b0, uint32_t b1) {
    asm volatile(
        "mma.sync.aligned.m16n8k16.row.col.f32.f16.f16.f32 "
        "{%0,%1,%2,%3}, {%4,%5,%6,%7}, {%8,%9}, {%0,%1,%2,%3};"
        : "+f"(d[0]), "+f"(d[1]), "+f"(d[2]), "+f"(d[3])
        : "r"(a[0]), "r"(a[1]), "r"(a[2]), "r"(a[3]), "r"(b0), "r"(b1));
}

__device__ __forceinline__ void ldsm_x4(uint32_t& d0, uint32_t& d1,
                                        uint32_t& d2, uint32_t& d3,
                                        uint32_t saddr) {
    asm volatile("ldmatrix.sync.aligned.m8n8.x4.shared.b16 {%0,%1,%2,%3}, [%4];"
                 : "=r"(d0), "=r"(d1), "=r"(d2), "=r"(d3) : "r"(saddr));
}

__device__ __forceinline__ void ldsm_x4_t(uint32_t& d0, uint32_t& d1,
                                          uint32_t& d2, uint32_t& d3,
                                          uint32_t saddr) {
    asm volatile("ldmatrix.sync.aligned.m8n8.x4.trans.shared.b16 {%0,%1,%2,%3}, [%4];"
                 : "=r"(d0), "=r"(d1), "=r"(d2), "=r"(d3) : "r"(saddr));
}

__device__ __forceinline__ uint32_t smem_u32(const void* p) {
    uint32_t a;
    asm("{ .reg .u64 t; cvta.to.shared.u64 t, %1; cvt.u32.u64 %0, t; }"
        : "=r"(a) : "l"(p));
    return a;
}

__device__ __forceinline__ uint32_t h2pack(float x, float y) {
    __half2 h = __floats2half2_rn(x, y);
    return *(uint32_t*)&h;
}

// ---------------------------------------------------------------------------
// Kernel 0a: transpose+fuse weights -> fp16 g_wth[n][k]
// ---------------------------------------------------------------------------
__global__ void wtrans(const float* __restrict__ Wq,
                       const float* __restrict__ Wk,
                       const float* __restrict__ Wv)
{
    int idx = blockIdx.x * 256 + threadIdx.x;   // 73728 half2 words
    int n = idx / (Cc / 2), kw = idx % (Cc / 2);
    const float* W = (n < 64) ? Wq : (n < 128 ? Wk : Wv);
    int col = n & 63;
    g_wth[idx] = h2pack(W[(size_t)(2 * kw) * Hh + col],
                        W[(size_t)(2 * kw + 1) * Hh + col]);
}

// ---------------------------------------------------------------------------
// Kernel 0b: x -> fp16 g_xh (8 floats per thread)
// ---------------------------------------------------------------------------
__global__ void xcvt(const float* __restrict__ x)
{
    int t = blockIdx.x * 256 + threadIdx.x;     // 1572864 threads
    const float4* xp = (const float4*)x;
    float4 a = xp[2 * t], b = xp[2 * t + 1];
    uint4 o;
    o.x = h2pack(a.x, a.y); o.y = h2pack(a.z, a.w);
    o.z = h2pack(b.x, b.y); o.w = h2pack(b.z, b.w);
    *(uint4*)&g_xh[4 * t] = o;
}

// ---------------------------------------------------------------------------
// Kernel 1: QKV projection, fp16 in/out, pure copy->ldmatrix->HMMA mainloop.
// CTA tile 128(M) x 192(N fused), BK=32, double-buffered.
// Rows padded to 20 words -> ldmatrix phases conflict-free.
// ---------------------------------------------------------------------------
#define BKh 32
#define NCH (Cc / BKh)         // 24
#define W_A 0                  // [2][128*20] words
#define W_B 5120               // [2][192*20] words
#define QKV_SMEM (12800 * 4)   // 51200 B

__global__ __launch_bounds__(256) void qkv_h()
{
    extern __shared__ uint32_t smw[];
    const uint32_t sb = smem_u32(smw);

    const int tid  = threadIdx.x;
    const int lane = tid & 31, wid = tid >> 5;
    const int m0   = blockIdx.x * 128;
    const int g    = lane >> 2, tig = lane & 3;
    const int wm   = wid & 3,  wn  = wid >> 2;

    // copy mappings: A 2 uint4/thread, B 3 uint4/thread per chunk
    int rowA[2], cwA[2], rowB[3], cwB[3];
#pragma unroll
    for (int r = 0; r < 2; r++) { int idx = r*256+tid; rowA[r]=idx>>2; cwA[r]=(idx&3)<<2; }
#pragma unroll
    for (int r = 0; r < 3; r++) { int idx = r*256+tid; rowB[r]=idx>>2; cwB[r]=(idx&3)<<2; }

    // ldmatrix lane-derived offsets
    const int a_lrow = wm * 32 + (lane & 15);
    const int a_kh   = ((lane >> 4) & 1) << 2;
    const int b_lrow = wn * 96 + ((lane >> 4) & 1) * 8 + (lane & 7);
    const int b_kh   = ((lane >> 3) & 1) << 2;

    float acc[2][12][4];
#pragma unroll
    for (int i = 0; i < 2; i++)
#pragma unroll
        for (int j = 0; j < 12; j++)
#pragma unroll
            for (int r = 0; r < 4; r++) acc[i][j][r] = 0.f;

    // prologue: chunk 0 -> buffer 0
#pragma unroll
    for (int r = 0; r < 2; r++)
        *(uint4*)&smw[W_A + rowA[r] * 20 + cwA[r]] =
            *(const uint4*)&g_xh[(size_t)(m0 + rowA[r]) * (Cc/2) + cwA[r]];
#pragma unroll
    for (int r = 0; r < 3; r++)
        *(uint4*)&smw[W_B + rowB[r] * 20 + cwB[r]] =
            *(const uint4*)&g_wth[(size_t)rowB[r] * (Cc/2) + cwB[r]];
    __syncthreads();

    for (int t = 0; t < NCH; t++) {
        const int buf = t & 1;
        uint4 stA[2], stB[3];
        if (t + 1 < NCH) {
            const int k0w = (t + 1) * (BKh / 2);
#pragma unroll
            for (int r = 0; r < 2; r++)
                stA[r] = *(const uint4*)&g_xh[(size_t)(m0 + rowA[r]) * (Cc/2) + k0w + cwA[r]];
#pragma unroll
            for (int r = 0; r < 3; r++)
                stB[r] = *(const uint4*)&g_wth[(size_t)rowB[r] * (Cc/2) + k0w + cwB[r]];
        }

        const uint32_t Abase = sb + (W_A + buf * 2560) * 4;
        const uint32_t Bbase = sb + (W_B + buf * 3840) * 4;

#pragma unroll
        for (int kk2 = 0; kk2 < 16; kk2 += 8) {
            uint32_t a[2][4];
#pragma unroll
            for (int i = 0; i < 2; i++)
                ldsm_x4(a[i][0], a[i][1], a[i][2], a[i][3],
                        Abase + (uint32_t)(((a_lrow + i * 16) * 20 + kk2 + a_kh) * 4));
            uint32_t bf[12][2];
#pragma unroll
            for (int p = 0; p < 6; p++) {
                uint32_t d0, d1, d2, d3;
                ldsm_x4(d0, d1, d2, d3,
                        Bbase + (uint32_t)(((b_lrow + p * 16) * 20 + kk2 + b_kh) * 4));
                bf[2*p][0] = d0; bf[2*p][1] = d1;
                bf[2*p+1][0] = d2; bf[2*p+1][1] = d3;
            }
#pragma unroll
            for (int j = 0; j < 12; j++) {
                mma_fp16(acc[0][j], a[0], bf[j][0], bf[j][1]);
                mma_fp16(acc[1][j], a[1], bf[j][0], bf[j][1]);
            }
        }

        if (t + 1 < NCH) {
            uint32_t* Ad = smw + W_A + (buf ^ 1) * 2560;
            uint32_t* Bd = smw + W_B + (buf ^ 1) * 3840;
#pragma unroll
            for (int r = 0; r < 2; r++)
                *(uint4*)&Ad[rowA[r] * 20 + cwA[r]] = stA[r];
#pragma unroll
            for (int r = 0; r < 3; r++)
                *(uint4*)&Bd[rowB[r] * 20 + cwB[r]] = stB[r];
        }
        __syncthreads();
    }

    // epilogue: write fp16 q/k/v
#pragma unroll
    for (int i = 0; i < 2; i++) {
        int r0 = m0 + wm * 32 + i * 16 + g;
#pragma unroll
        for (int j = 0; j < 12; j++) {
            int c = wn * 96 + j * 8 + tig * 2;
            uint32_t* op = (c < 64) ? g_qh : (c < 128 ? g_kh : g_vh);
            int oc = (c & 63) >> 1;
            op[(size_t)r0 * 32 + oc]       = h2pack(acc[i][j][0], acc[i][j][1]);
            op[(size_t)(r0 + 8) * 32 + oc] = h2pack(acc[i][j][2], acc[i][j][3]);
        }
    }
}

// ---------------------------------------------------------------------------
// Kernel 2: causal flash attention, fp16 mma, fp16 staging (pure copies).
// V row-major [j][h]; PV B-fragments via ldmatrix.x4.trans (single pass).
// ---------------------------------------------------------------------------
#define OQ  0                      // 128*36
#define OK_ 4608                   // 64*36
#define OV  6912                   // 64*36
#define ATTN_SMEM (9216 * 4)       // 36864 B

__global__ __launch_bounds__(256) void attn_mma(
    const float* __restrict__ amask,
    float* __restrict__ out)
{
    extern __shared__ uint32_t smw[];
    uint32_t* Qs = smw + OQ;
    uint32_t* Ks = smw + OK_;
    uint32_t* Vs = smw + OV;
    const uint32_t sbv = smem_u32(smw) + OV * 4;

    const int b   = blockIdx.y;
    const int q0  = blockIdx.x * 128;
    const int tid = threadIdx.x;
    const int lane = tid & 31, w = tid >> 5;
    const int g = lane >> 2, t = lane & 3;

    // stage Q (straight copy of fp16 rows)
    const uint32_t* qp = g_qh + ((size_t)b * Tt + q0) * 32;
#pragma unroll
    for (int r = 0; r < 4; r++) {
        int idx = r * 256 + tid;
        int row = idx >> 3, cw = (idx & 7) << 2;
        *(uint4*)&Qs[row * 36 + cw] = *(const uint4*)&qp[row * 32 + cw];
    }

    float m0 = -INFINITY, m1 = -INFINITY, l0 = 0.f, l1 = 0.f;
    float o[8][4];
#pragma unroll
    for (int f = 0; f < 8; f++)
#pragma unroll
        for (int r = 0; r < 4; r++) o[f][r] = 0.f;

    const float am0 = amask[(size_t)b * Tt + q0 + w * 16 + g];
    const float am1 = amask[(size_t)b * Tt + q0 + w * 16 + g + 8];
    const int qg0 = q0 + w * 16 + g;
    const int qg1 = qg0 + 8;

    __syncthreads();

    const int jend = q0 + 64;
    for (int j0 = 0; j0 <= jend; j0 += 64) {
        const uint32_t* kp = g_kh + ((size_t)b * Tt + j0) * 32;
        const uint32_t* vp = g_vh + ((size_t)b * Tt + j0) * 32;
#pragma unroll
        for (int r = 0; r < 2; r++) {
            int idx = r * 256 + tid;
            int row = idx >> 3, cw = (idx & 7) << 2;
            *(uint4*)&Ks[row * 36 + cw] = *(const uint4*)&kp[row * 32 + cw];
            *(uint4*)&Vs[row * 36 + cw] = *(const uint4*)&vp[row * 32 + cw];
        }
        __syncthreads();

        // S = Q K^T
        float c[8][4];
#pragma unroll
        for (int f = 0; f < 8; f++)
#pragma unroll
            for (int r = 0; r < 4; r++) c[f][r] = 0.f;
#pragma unroll
        for (int ks = 0; ks < 4; ks++) {
            uint32_t a[4];
            int base = (w * 16 + g) * 36 + ks * 8 + t;
            a[0] = Qs[base];
            a[1] = Qs[base + 8 * 36];
            a[2] = Qs[base + 4];
            a[3] = Qs[base + 8 * 36 + 4];
#pragma unroll
            for (int f = 0; f < 8; f++) {
                int nb = (f * 8 + g) * 36 + ks * 8 + t;
                mma_fp16(c[f], a, Ks[nb], Ks[nb + 4]);
            }
        }

        // masks
        float mx0 = -INFINITY, mx1 = -INFINITY;
#pragma unroll
        for (int f = 0; f < 8; f++) {
            int col = j0 + f * 8 + t * 2;
            float v0 = c[f][0] * 0.125f * am0;
            float v1 = c[f][1] * 0.125f * am0;
            float v2 = c[f][2] * 0.125f * am1;
            float v3 = c[f][3] * 0.125f * am1;
            if (v0 == 0.f || col     > qg0) v0 = -INFINITY;
            if (v1 == 0.f || col + 1 > qg0) v1 = -INFINITY;
            if (v2 == 0.f || col     > qg1) v2 = -INFINITY;
            if (v3 == 0.f || col + 1 > qg1) v3 = -INFINITY;
            c[f][0] = v0; c[f][1] = v1; c[f][2] = v2; c[f][3] = v3;
            mx0 = fmaxf(mx0, fmaxf(v0, v1));
            mx1 = fmaxf(mx1, fmaxf(v2, v3));
        }
        mx0 = fmaxf(mx0, __shfl_xor_sync(0xffffffffu, mx0, 1));
        mx0 = fmaxf(mx0, __shfl_xor_sync(0xffffffffu, mx0, 2));
        mx1 = fmaxf(mx1, __shfl_xor_sync(0xffffffffu, mx1, 1));
        mx1 = fmaxf(mx1, __shfl_xor_sync(0xffffffffu, mx1, 2));

        float mn0 = fmaxf(m0, mx0), mn1 = fmaxf(m1, mx1);
        float alpha0, alpha1, ls0 = 0.f, ls1 = 0.f;
        uint32_t p01[8], p23[8];
        if (mn0 == -INFINITY) {
            alpha0 = 1.f;
#pragma unroll
            for (int f = 0; f < 8; f++) { c[f][0] = 0.f; c[f][1] = 0.f; }
        } else {
            alpha0 = __expf(m0 - mn0);
#pragma unroll
            for (int f = 0; f < 8; f++) {
                c[f][0] = __expf(c[f][0] - mn0);
                c[f][1] = __expf(c[f][1] - mn0);
                ls0 += c[f][0] + c[f][1];
            }
        }
        if (mn1 == -INFINITY) {
            alpha1 = 1.f;
#pragma unroll
            for (int f = 0; f < 8; f++) { c[f][2] = 0.f; c[f][3] = 0.f; }
        } else {
            alpha1 = __expf(m1 - mn1);
#pragma unroll
            for (int f = 0; f < 8; f++) {
                c[f][2] = __expf(c[f][2] - mn1);
                c[f][3] = __expf(c[f][3] - mn1);
                ls1 += c[f][2] + c[f][3];
            }
        }
        m0 = mn0; m1 = mn1;
        ls0 += __shfl_xor_sync(0xffffffffu, ls0, 1);
        ls0 += __shfl_xor_sync(0xffffffffu, ls0, 2);
        ls1 += __shfl_xor_sync(0xffffffffu, ls1, 1);
        ls1 += __shfl_xor_sync(0xffffffffu, ls1, 2);
        l0 = l0 * alpha0 + ls0;
        l1 = l1 * alpha1 + ls1;

#pragma unroll
        for (int f = 0; f < 8; f++) {
            p01[f] = h2pack(c[f][0], c[f][1]);
            p23[f] = h2pack(c[f][2], c[f][3]);
            o[f][0] *= alpha0; o[f][1] *= alpha0;
            o[f][2] *= alpha1; o[f][3] *= alpha1;
        }

        // O += P V (single pass; B-frags via ldmatrix.trans from [j][h])
        const int vrow = (lane & 15);
        const int vcb  = ((lane >> 4) & 1) << 2;
#pragma unroll
        for (int s = 0; s < 4; s++) {
            uint32_t a[4];
            a[0] = p01[2 * s];     a[1] = p23[2 * s];
            a[2] = p01[2 * s + 1]; a[3] = p23[2 * s + 1];
#pragma unroll
            for (int p = 0; p < 4; p++) {
                uint32_t d0, d1, d2, d3;
                ldsm_x4_t(d0, d1, d2, d3,
                          sbv + (uint32_t)((((s * 16 + vrow) * 36) + p * 8 + vcb) * 4));
                mma_fp16(o[2 * p],     a, d0, d1);
                mma_fp16(o[2 * p + 1], a, d2, d3);
            }
        }
        __syncthreads();
    }

    float inv0 = (l0 > 0.f) ? (1.f / l0) : 0.f;
    float inv1 = (l1 > 0.f) ? (1.f / l1) : 0.f;
    float* op0 = out + ((size_t)b * Tt + qg0) * Hh;
    float* op1 = out + ((size_t)b * Tt + qg1) * Hh;
#pragma unroll
    for (int f = 0; f < 8; f++) {
        int col = f * 8 + t * 2;
        *(float2*)(op0 + col) = make_float2(o[f][0] * inv0, o[f][1] * inv0);
        *(float2*)(op1 + col) = make_float2(o[f][2] * inv1, o[f][3] * inv1);
    }
}

// ---------------------------------------------------------------------------
extern "C" void kernel_launch(void* const* d_in, const int* in_sizes, int n_in,
                              void* d_out, int out_size)
{
    const float* x  = (const float*)d_in[0];
    const float* am = (const float*)d_in[1];
    const float* Wq = (const float*)d_in[2];
    const float* Wk = (const float*)d_in[3];
    const float* Wv = (const float*)d_in[4];
    float*       out = (float*)d_out;

    wtrans<<<(192 * Cc / 2) / 256, 256>>>(Wq, Wk, Wv);
    xcvt<<<(M_TOT * Cc / 8) / 256, 256>>>(x);

    cudaFuncSetAttribute(qkv_h,
                         cudaFuncAttributeMaxDynamicSharedMemorySize, QKV_SMEM);
    qkv_h<<<M_TOT / 128, 256, QKV_SMEM>>>();

    cudaFuncSetAttribute(attn_mma,
                         cudaFuncAttributeMaxDynamicSharedMemorySize, ATTN_SMEM);
    dim3 g2(Tt / 128, Bb);
    attn_mma<<<g2, 256, ATTN_SMEM>>>(am, out);
}

// round 10
// speedup vs baseline: 4.9834x; 1.0663x over previous
#include <cuda_runtime.h>
#include <cuda_fp16.h>
#include <math.h>
#include <stdint.h>

#define Bb 8
#define Tt 2048
#define Cc 768
#define Hh 64
#define M_TOT (Bb*Tt)

// fp16 scratch (half2 packed in uint32)
__device__ uint32_t g_xh[M_TOT*Cc/2];    // x as fp16 [row][k]
__device__ uint32_t g_wth[192*Cc/2];     // fused transposed weights fp16 [n][k]
__device__ uint32_t g_qh[M_TOT*32];      // q fp16 [row][h]
__device__ uint32_t g_kh[M_TOT*32];
__device__ uint32_t g_vh[M_TOT*32];
// split-KV partials
__device__ float g_po[2 * M_TOT * 64];   // unnormalized O per split
__device__ float g_pm[2 * M_TOT];
__device__ float g_pl[2 * M_TOT];

// ---------------------------------------------------------------------------
// helpers
// ---------------------------------------------------------------------------
__device__ __forceinline__ void mma_fp16(float* d, const uint32_t* a,
                                         uint32_t b0, uint32_t b1) {
    asm volatile(
        "mma.sync.aligned.m16n8k16.row.col.f32.f16.f16.f32 "
        "{%0,%1,%2,%3}, {%4,%5,%6,%7}, {%8,%9}, {%0,%1,%2,%3};"
        : "+f"(d[0]), "+f"(d[1]), "+f"(d[2]), "+f"(d[3])
        : "r"(a[0]), "r"(a[1]), "r"(a[2]), "r"(a[3]), "r"(b0), "r"(b1));
}

__device__ __forceinline__ void ldsm_x4(uint32_t& d0, uint32_t& d1,
                                        uint32_t& d2, uint32_t& d3,
                                        uint32_t saddr) {
    asm volatile("ldmatrix.sync.aligned.m8n8.x4.shared.b16 {%0,%1,%2,%3}, [%4];"
                 : "=r"(d0), "=r"(d1), "=r"(d2), "=r"(d3) : "r"(saddr));
}

__device__ __forceinline__ void ldsm_x4_t(uint32_t& d0, uint32_t& d1,
                                          uint32_t& d2, uint32_t& d3,
                                          uint32_t saddr) {
    asm volatile("ldmatrix.sync.aligned.m8n8.x4.trans.shared.b16 {%0,%1,%2,%3}, [%4];"
                 : "=r"(d0), "=r"(d1), "=r"(d2), "=r"(d3) : "r"(saddr));
}

__device__ __forceinline__ uint32_t smem_u32(const void* p) {
    uint32_t a;
    asm("{ .reg .u64 t; cvta.to.shared.u64 t, %1; cvt.u32.u64 %0, t; }"
        : "=r"(a) : "l"(p));
    return a;
}

__device__ __forceinline__ uint32_t h2pack(float x, float y) {
    __half2 h = __floats2half2_rn(x, y);
    return *(uint32_t*)&h;
}

// ---------------------------------------------------------------------------
// Kernel 0a: transpose+fuse weights -> fp16 g_wth[n][k]
// ---------------------------------------------------------------------------
__global__ void wtrans(const float* __restrict__ Wq,
                       const float* __restrict__ Wk,
                       const float* __restrict__ Wv)
{
    int idx = blockIdx.x * 256 + threadIdx.x;
    int n = idx / (Cc / 2), kw = idx % (Cc / 2);
    const float* W = (n < 64) ? Wq : (n < 128 ? Wk : Wv);
    int col = n & 63;
    g_wth[idx] = h2pack(W[(size_t)(2 * kw) * Hh + col],
                        W[(size_t)(2 * kw + 1) * Hh + col]);
}

// ---------------------------------------------------------------------------
// Kernel 0b: x -> fp16 g_xh
// ---------------------------------------------------------------------------
__global__ void xcvt(const float* __restrict__ x)
{
    int t = blockIdx.x * 256 + threadIdx.x;
    const float4* xp = (const float4*)x;
    float4 a = xp[2 * t], b = xp[2 * t + 1];
    uint4 o;
    o.x = h2pack(a.x, a.y); o.y = h2pack(a.z, a.w);
    o.z = h2pack(b.x, b.y); o.w = h2pack(b.z, b.w);
    *(uint4*)&g_xh[4 * t] = o;
}

// ---------------------------------------------------------------------------
// Kernel 1: QKV projection (unchanged from R9).
// ---------------------------------------------------------------------------
#define BKh 32
#define NCH (Cc / BKh)
#define W_A 0
#define W_B 5120
#define QKV_SMEM (12800 * 4)

__global__ __launch_bounds__(256) void qkv_h()
{
    extern __shared__ uint32_t smw[];
    const uint32_t sb = smem_u32(smw);

    const int tid  = threadIdx.x;
    const int lane = tid & 31, wid = tid >> 5;
    const int m0   = blockIdx.x * 128;
    const int g    = lane >> 2, tig = lane & 3;
    const int wm   = wid & 3,  wn  = wid >> 2;

    int rowA[2], cwA[2], rowB[3], cwB[3];
#pragma unroll
    for (int r = 0; r < 2; r++) { int idx = r*256+tid; rowA[r]=idx>>2; cwA[r]=(idx&3)<<2; }
#pragma unroll
    for (int r = 0; r < 3; r++) { int idx = r*256+tid; rowB[r]=idx>>2; cwB[r]=(idx&3)<<2; }

    const int a_lrow = wm * 32 + (lane & 15);
    const int a_kh   = ((lane >> 4) & 1) << 2;
    const int b_lrow = wn * 96 + ((lane >> 4) & 1) * 8 + (lane & 7);
    const int b_kh   = ((lane >> 3) & 1) << 2;

    float acc[2][12][4];
#pragma unroll
    for (int i = 0; i < 2; i++)
#pragma unroll
        for (int j = 0; j < 12; j++)
#pragma unroll
            for (int r = 0; r < 4; r++) acc[i][j][r] = 0.f;

#pragma unroll
    for (int r = 0; r < 2; r++)
        *(uint4*)&smw[W_A + rowA[r] * 20 + cwA[r]] =
            *(const uint4*)&g_xh[(size_t)(m0 + rowA[r]) * (Cc/2) + cwA[r]];
#pragma unroll
    for (int r = 0; r < 3; r++)
        *(uint4*)&smw[W_B + rowB[r] * 20 + cwB[r]] =
            *(const uint4*)&g_wth[(size_t)rowB[r] * (Cc/2) + cwB[r]];
    __syncthreads();

    for (int t = 0; t < NCH; t++) {
        const int buf = t & 1;
        uint4 stA[2], stB[3];
        if (t + 1 < NCH) {
            const int k0w = (t + 1) * (BKh / 2);
#pragma unroll
            for (int r = 0; r < 2; r++)
                stA[r] = *(const uint4*)&g_xh[(size_t)(m0 + rowA[r]) * (Cc/2) + k0w + cwA[r]];
#pragma unroll
            for (int r = 0; r < 3; r++)
                stB[r] = *(const uint4*)&g_wth[(size_t)rowB[r] * (Cc/2) + k0w + cwB[r]];
        }

        const uint32_t Abase = sb + (W_A + buf * 2560) * 4;
        const uint32_t Bbase = sb + (W_B + buf * 3840) * 4;

#pragma unroll
        for (int kk2 = 0; kk2 < 16; kk2 += 8) {
            uint32_t a[2][4];
#pragma unroll
            for (int i = 0; i < 2; i++)
                ldsm_x4(a[i][0], a[i][1], a[i][2], a[i][3],
                        Abase + (uint32_t)(((a_lrow + i * 16) * 20 + kk2 + a_kh) * 4));
            uint32_t bf[12][2];
#pragma unroll
            for (int p = 0; p < 6; p++) {
                uint32_t d0, d1, d2, d3;
                ldsm_x4(d0, d1, d2, d3,
                        Bbase + (uint32_t)(((b_lrow + p * 16) * 20 + kk2 + b_kh) * 4));
                bf[2*p][0] = d0; bf[2*p][1] = d1;
                bf[2*p+1][0] = d2; bf[2*p+1][1] = d3;
            }
#pragma unroll
            for (int j = 0; j < 12; j++) {
                mma_fp16(acc[0][j], a[0], bf[j][0], bf[j][1]);
                mma_fp16(acc[1][j], a[1], bf[j][0], bf[j][1]);
            }
        }

        if (t + 1 < NCH) {
            uint32_t* Ad = smw + W_A + (buf ^ 1) * 2560;
            uint32_t* Bd = smw + W_B + (buf ^ 1) * 3840;
#pragma unroll
            for (int r = 0; r < 2; r++)
                *(uint4*)&Ad[rowA[r] * 20 + cwA[r]] = stA[r];
#pragma unroll
            for (int r = 0; r < 3; r++)
                *(uint4*)&Bd[rowB[r] * 20 + cwB[r]] = stB[r];
        }
        __syncthreads();
    }

#pragma unroll
    for (int i = 0; i < 2; i++) {
        int r0 = m0 + wm * 32 + i * 16 + g;
#pragma unroll
        for (int j = 0; j < 12; j++) {
            int c = wn * 96 + j * 8 + tig * 2;
            uint32_t* op = (c < 64) ? g_qh : (c < 128 ? g_kh : g_vh);
            int oc = (c & 63) >> 1;
            op[(size_t)r0 * 32 + oc]       = h2pack(acc[i][j][0], acc[i][j][1]);
            op[(size_t)(r0 + 8) * 32 + oc] = h2pack(acc[i][j][2], acc[i][j][3]);
        }
    }
}

// ---------------------------------------------------------------------------
// Kernel 2: causal flash attention, split-KV x2 + double-buffered K/V.
// Writes unnormalized partial O + (m,l) per split; combine kernel merges.
// smem: Q 128x36 | 2 x (K 64x36, V 64x36)
// ---------------------------------------------------------------------------
#define OQ  0                      // 4608 words
#define OKV 4608                   // buffer stride 4608 (K 2304 + V 2304)
#define ATTN_SMEM (13824 * 4)      // 55296 B

__global__ __launch_bounds__(256) void attn_mma(
    const float* __restrict__ amask)
{
    extern __shared__ uint32_t smw[];
    uint32_t* Qs = smw + OQ;
    const uint32_t sb = smem_u32(smw);

    const int b   = blockIdx.y;
    const int iq  = (int)gridDim.x - 1 - (int)blockIdx.x;   // long blocks first
    const int s   = blockIdx.z;
    const int q0  = iq * 128;
    const int tid = threadIdx.x;
    const int lane = tid & 31, w = tid >> 5;
    const int g = lane >> 2, t = lane & 3;

    const int ntiles = 2 * iq + 2;
    const int half   = ntiles >> 1;
    const int tstart = s * half;
    const int tend   = tstart + half;

    // stage Q
    const uint32_t* qp = g_qh + ((size_t)b * Tt + q0) * 32;
#pragma unroll
    for (int r = 0; r < 4; r++) {
        int idx = r * 256 + tid;
        int row = idx >> 3, cw = (idx & 7) << 2;
        *(uint4*)&Qs[row * 36 + cw] = *(const uint4*)&qp[row * 32 + cw];
    }

    float m0 = -INFINITY, m1 = -INFINITY, l0 = 0.f, l1 = 0.f;
    float o[8][4];
#pragma unroll
    for (int f = 0; f < 8; f++)
#pragma unroll
        for (int r = 0; r < 4; r++) o[f][r] = 0.f;

    const float am0 = amask[(size_t)b * Tt + q0 + w * 16 + g];
    const float am1 = amask[(size_t)b * Tt + q0 + w * 16 + g + 8];
    const int qg0 = q0 + w * 16 + g;
    const int qg1 = qg0 + 8;

    // staging mapping (2 uint4 each for K and V per thread)
    int srow[2], scw[2];
#pragma unroll
    for (int r = 0; r < 2; r++) { int idx = r*256+tid; srow[r]=idx>>3; scw[r]=(idx&7)<<2; }

    // prologue: stage tile tstart into buffer 0
    {
        const uint32_t* kp = g_kh + ((size_t)b * Tt + tstart * 64) * 32;
        const uint32_t* vp = g_vh + ((size_t)b * Tt + tstart * 64) * 32;
        uint32_t* Kd = smw + OKV;
        uint32_t* Vd = smw + OKV + 2304;
#pragma unroll
        for (int r = 0; r < 2; r++) {
            *(uint4*)&Kd[srow[r] * 36 + scw[r]] = *(const uint4*)&kp[srow[r] * 32 + scw[r]];
            *(uint4*)&Vd[srow[r] * 36 + scw[r]] = *(const uint4*)&vp[srow[r] * 32 + scw[r]];
        }
    }
    __syncthreads();

    for (int tt = tstart; tt < tend; tt++) {
        const int cur = (tt - tstart) & 1;
        const int j0 = tt * 64;
        const bool more = (tt + 1 < tend);

        uint4 stK[2], stV[2];
        if (more) {
            const uint32_t* kp = g_kh + ((size_t)b * Tt + (tt + 1) * 64) * 32;
            const uint32_t* vp = g_vh + ((size_t)b * Tt + (tt + 1) * 64) * 32;
#pragma unroll
            for (int r = 0; r < 2; r++) {
                stK[r] = *(const uint4*)&kp[srow[r] * 32 + scw[r]];
                stV[r] = *(const uint4*)&vp[srow[r] * 32 + scw[r]];
            }
        }

        const uint32_t* Ks = smw + OKV + cur * 4608;
        const uint32_t sbv = sb + (uint32_t)((OKV + cur * 4608 + 2304) * 4);

        // S = Q K^T
        float c[8][4];
#pragma unroll
        for (int f = 0; f < 8; f++)
#pragma unroll
            for (int r = 0; r < 4; r++) c[f][r] = 0.f;
#pragma unroll
        for (int ks = 0; ks < 4; ks++) {
            uint32_t a[4];
            int base = (w * 16 + g) * 36 + ks * 8 + t;
            a[0] = Qs[base];
            a[1] = Qs[base + 8 * 36];
            a[2] = Qs[base + 4];
            a[3] = Qs[base + 8 * 36 + 4];
#pragma unroll
            for (int f = 0; f < 8; f++) {
                int nb = (f * 8 + g) * 36 + ks * 8 + t;
                mma_fp16(c[f], a, Ks[nb], Ks[nb + 4]);
            }
        }

        // masks
        float mx0 = -INFINITY, mx1 = -INFINITY;
#pragma unroll
        for (int f = 0; f < 8; f++) {
            int col = j0 + f * 8 + t * 2;
            float v0 = c[f][0] * 0.125f * am0;
            float v1 = c[f][1] * 0.125f * am0;
            float v2 = c[f][2] * 0.125f * am1;
            float v3 = c[f][3] * 0.125f * am1;
            if (v0 == 0.f || col     > qg0) v0 = -INFINITY;
            if (v1 == 0.f || col + 1 > qg0) v1 = -INFINITY;
            if (v2 == 0.f || col     > qg1) v2 = -INFINITY;
            if (v3 == 0.f || col + 1 > qg1) v3 = -INFINITY;
            c[f][0] = v0; c[f][1] = v1; c[f][2] = v2; c[f][3] = v3;
            mx0 = fmaxf(mx0, fmaxf(v0, v1));
            mx1 = fmaxf(mx1, fmaxf(v2, v3));
        }
        mx0 = fmaxf(mx0, __shfl_xor_sync(0xffffffffu, mx0, 1));
        mx0 = fmaxf(mx0, __shfl_xor_sync(0xffffffffu, mx0, 2));
        mx1 = fmaxf(mx1, __shfl_xor_sync(0xffffffffu, mx1, 1));
        mx1 = fmaxf(mx1, __shfl_xor_sync(0xffffffffu, mx1, 2));

        float mn0 = fmaxf(m0, mx0), mn1 = fmaxf(m1, mx1);
        float alpha0, alpha1, ls0 = 0.f, ls1 = 0.f;
        uint32_t p01[8], p23[8];
        if (mn0 == -INFINITY) {
            alpha0 = 1.f;
#pragma unroll
            for (int f = 0; f < 8; f++) { c[f][0] = 0.f; c[f][1] = 0.f; }
        } else {
            alpha0 = __expf(m0 - mn0);
#pragma unroll
            for (int f = 0; f < 8; f++) {
                c[f][0] = __expf(c[f][0] - mn0);
                c[f][1] = __expf(c[f][1] - mn0);
                ls0 += c[f][0] + c[f][1];
            }
        }
        if (mn1 == -INFINITY) {
            alpha1 = 1.f;
#pragma unroll
            for (int f = 0; f < 8; f++) { c[f][2] = 0.f; c[f][3] = 0.f; }
        } else {
            alpha1 = __expf(m1 - mn1);
#pragma unroll
            for (int f = 0; f < 8; f++) {
                c[f][2] = __expf(c[f][2] - mn1);
                c[f][3] = __expf(c[f][3] - mn1);
                ls1 += c[f][2] + c[f][3];
            }
        }
        m0 = mn0; m1 = mn1;
        ls0 += __shfl_xor_sync(0xffffffffu, ls0, 1);
        ls0 += __shfl_xor_sync(0xffffffffu, ls0, 2);
        ls1 += __shfl_xor_sync(0xffffffffu, ls1, 1);
        ls1 += __shfl_xor_sync(0xffffffffu, ls1, 2);
        l0 = l0 * alpha0 + ls0;
        l1 = l1 * alpha1 + ls1;

#pragma unroll
        for (int f = 0; f < 8; f++) {
            p01[f] = h2pack(c[f][0], c[f][1]);
            p23[f] = h2pack(c[f][2], c[f][3]);
            o[f][0] *= alpha0; o[f][1] *= alpha0;
            o[f][2] *= alpha1; o[f][3] *= alpha1;
        }

        // O += P V (B-frags via ldmatrix.trans from [j][h])
        const int vrow = (lane & 15);
        const int vcb  = ((lane >> 4) & 1) << 2;
#pragma unroll
        for (int ss = 0; ss < 4; ss++) {
            uint32_t a[4];
            a[0] = p01[2 * ss];     a[1] = p23[2 * ss];
            a[2] = p01[2 * ss + 1]; a[3] = p23[2 * ss + 1];
#pragma unroll
            for (int p = 0; p < 4; p++) {
                uint32_t d0, d1, d2, d3;
                ldsm_x4_t(d0, d1, d2, d3,
                          sbv + (uint32_t)((((ss * 16 + vrow) * 36) + p * 8 + vcb) * 4));
                mma_fp16(o[2 * p],     a, d0, d1);
                mma_fp16(o[2 * p + 1], a, d2, d3);
            }
        }

        // stage next tile into the other buffer
        if (more) {
            uint32_t* Kd = smw + OKV + (cur ^ 1) * 4608;
            uint32_t* Vd = Kd + 2304;
#pragma unroll
            for (int r = 0; r < 2; r++) {
                *(uint4*)&Kd[srow[r] * 36 + scw[r]] = stK[r];
                *(uint4*)&Vd[srow[r] * 36 + scw[r]] = stV[r];
            }
        }
        __syncthreads();
    }

    // epilogue: write unnormalized partials
    float* po0 = g_po + ((size_t)s * M_TOT + (size_t)b * Tt + qg0) * 64;
    float* po1 = g_po + ((size_t)s * M_TOT + (size_t)b * Tt + qg1) * 64;
#pragma unroll
    for (int f = 0; f < 8; f++) {
        int col = f * 8 + t * 2;
        *(float2*)(po0 + col) = make_float2(o[f][0], o[f][1]);
        *(float2*)(po1 + col) = make_float2(o[f][2], o[f][3]);
    }
    if (t == 0) {
        size_t r0 = (size_t)s * M_TOT + (size_t)b * Tt + qg0;
        size_t r1 = (size_t)s * M_TOT + (size_t)b * Tt + qg1;
        g_pm[r0] = m0; g_pl[r0] = l0;
        g_pm[r1] = m1; g_pl[r1] = l1;
    }
}

// ---------------------------------------------------------------------------
// Kernel 3: combine two splits
// ---------------------------------------------------------------------------
__global__ void combine(float* __restrict__ out)
{
    int idx = blockIdx.x * 256 + threadIdx.x;   // M_TOT*16 float4 lanes
    int row = idx >> 4;
    int c4  = (idx & 15) << 2;
    float m0 = g_pm[row], m1 = g_pm[M_TOT + row];
    float l0 = g_pl[row], l1 = g_pl[M_TOT + row];
    float M = fmaxf(m0, m1);
    float w0 = (m0 == -INFINITY) ? 0.f : __expf(m0 - M);
    float w1 = (m1 == -INFINITY) ? 0.f : __expf(m1 - M);
    float l = l0 * w0 + l1 * w1;
    float inv = (l > 0.f) ? (1.f / l) : 0.f;
    float4 a  = *(const float4*)&g_po[(size_t)row * 64 + c4];
    float4 bb = *(const float4*)&g_po[(size_t)(M_TOT + row) * 64 + c4];
    float4 r;
    r.x = (a.x * w0 + bb.x * w1) * inv;
    r.y = (a.y * w0 + bb.y * w1) * inv;
    r.z = (a.z * w0 + bb.z * w1) * inv;
    r.w = (a.w * w0 + bb.w * w1) * inv;
    *(float4*)&out[(size_t)row * 64 + c4] = r;
}

// ---------------------------------------------------------------------------
extern "C" void kernel_launch(void* const* d_in, const int* in_sizes, int n_in,
                              void* d_out, int out_size)
{
    const float* x  = (const float*)d_in[0];
    const float* am = (const float*)d_in[1];
    const float* Wq = (const float*)d_in[2];
    const float* Wk = (const float*)d_in[3];
    const float* Wv = (const float*)d_in[4];
    float*       out = (float*)d_out;

    wtrans<<<(192 * Cc / 2) / 256, 256>>>(Wq, Wk, Wv);
    xcvt<<<(M_TOT * Cc / 8) / 256, 256>>>(x);

    cudaFuncSetAttribute(qkv_h,
                         cudaFuncAttributeMaxDynamicSharedMemorySize, QKV_SMEM);
    qkv_h<<<M_TOT / 128, 256, QKV_SMEM>>>();

    cudaFuncSetAttribute(attn_mma,
                         cudaFuncAttributeMaxDynamicSharedMemorySize, ATTN_SMEM);
    dim3 g2(Tt / 128, Bb, 2);
    attn_mma<<<g2, 256, ATTN_SMEM>>>(am);

    combine<<<(M_TOT * 16) / 256, 256>>>(out);
}

// round 11
// speedup vs baseline: 4.9852x; 1.0004x over previous
#include <cuda_runtime.h>
#include <cuda_fp16.h>
#include <math.h>
#include <stdint.h>

#define Bb 8
#define Tt 2048
#define Cc 768
#define Hh 64
#define M_TOT (Bb*Tt)

// fp16 scratch (half2 packed in uint32)
__device__ uint32_t g_xh[M_TOT*Cc/2];    // x as fp16 [row][k]
__device__ uint32_t g_wth[192*Cc/2];     // fused transposed weights fp16 [n][k]
__device__ uint32_t g_qh[M_TOT*32];      // q fp16 [row][h]
__device__ uint32_t g_kh[M_TOT*32];
__device__ uint32_t g_vh[M_TOT*32];
// split-KV partials
__device__ float g_po[2 * M_TOT * 64];   // unnormalized O per split
__device__ float g_pm[2 * M_TOT];
__device__ float g_pl[2 * M_TOT];

// ---------------------------------------------------------------------------
// helpers
// ---------------------------------------------------------------------------
__device__ __forceinline__ void mma_fp16(float* d, const uint32_t* a,
                                         uint32_t b0, uint32_t b1) {
    asm volatile(
        "mma.sync.aligned.m16n8k16.row.col.f32.f16.f16.f32 "
        "{%0,%1,%2,%3}, {%4,%5,%6,%7}, {%8,%9}, {%0,%1,%2,%3};"
        : "+f"(d[0]), "+f"(d[1]), "+f"(d[2]), "+f"(d[3])
        : "r"(a[0]), "r"(a[1]), "r"(a[2]), "r"(a[3]), "r"(b0), "r"(b1));
}

__device__ __forceinline__ void ldsm_x4(uint32_t& d0, uint32_t& d1,
                                        uint32_t& d2, uint32_t& d3,
                                        uint32_t saddr) {
    asm volatile("ldmatrix.sync.aligned.m8n8.x4.shared.b16 {%0,%1,%2,%3}, [%4];"
                 : "=r"(d0), "=r"(d1), "=r"(d2), "=r"(d3) : "r"(saddr));
}

__device__ __forceinline__ void ldsm_x4_t(uint32_t& d0, uint32_t& d1,
                                          uint32_t& d2, uint32_t& d3,
                                          uint32_t saddr) {
    asm volatile("ldmatrix.sync.aligned.m8n8.x4.trans.shared.b16 {%0,%1,%2,%3}, [%4];"
                 : "=r"(d0), "=r"(d1), "=r"(d2), "=r"(d3) : "r"(saddr));
}

__device__ __forceinline__ uint32_t smem_u32(const void* p) {
    uint32_t a;
    asm("{ .reg .u64 t; cvta.to.shared.u64 t, %1; cvt.u32.u64 %0, t; }"
        : "=r"(a) : "l"(p));
    return a;
}

__device__ __forceinline__ uint32_t h2pack(float x, float y) {
    __half2 h = __floats2half2_rn(x, y);
    return *(uint32_t*)&h;
}

// ---------------------------------------------------------------------------
// Kernel 0a: transpose+fuse weights -> fp16 g_wth[n][k]
// smem 64x64 transpose: coalesced LDG and STG.
// grid = 36 blocks (3 weights x 12 k-chunks), 256 threads.
// ---------------------------------------------------------------------------
__global__ void wtrans(const float* __restrict__ Wq,
                       const float* __restrict__ Wk,
                       const float* __restrict__ Wv)
{
    __shared__ float s[64][65];
    const int wsel = blockIdx.x / 12;
    const int k0   = (blockIdx.x % 12) * 64;
    const float* W = (wsel == 0) ? Wq : (wsel == 1 ? Wk : Wv);
    const int tid = threadIdx.x;

#pragma unroll
    for (int r = 0; r < 16; r++) {
        int idx = r * 256 + tid;
        int k = idx >> 6, h = idx & 63;
        s[k][h] = W[(size_t)(k0 + k) * Hh + h];
    }
    __syncthreads();

#pragma unroll
    for (int r = 0; r < 8; r++) {
        int idx = r * 256 + tid;
        int h = idx >> 5, kw = idx & 31;
        g_wth[(size_t)(wsel * 64 + h) * (Cc / 2) + (k0 >> 1) + kw] =
            h2pack(s[2 * kw][h], s[2 * kw + 1][h]);
    }
}

// ---------------------------------------------------------------------------
// Kernel 0b: x -> fp16 g_xh
// ---------------------------------------------------------------------------
__global__ void xcvt(const float* __restrict__ x)
{
    int t = blockIdx.x * 256 + threadIdx.x;
    const float4* xp = (const float4*)x;
    float4 a = xp[2 * t], b = xp[2 * t + 1];
    uint4 o;
    o.x = h2pack(a.x, a.y); o.y = h2pack(a.z, a.w);
    o.z = h2pack(b.x, b.y); o.w = h2pack(b.z, b.w);
    *(uint4*)&g_xh[4 * t] = o;
}

// ---------------------------------------------------------------------------
// Kernel 1: QKV projection (unchanged).
// ---------------------------------------------------------------------------
#define BKh 32
#define NCH (Cc / BKh)
#define W_A 0
#define W_B 5120
#define QKV_SMEM (12800 * 4)

__global__ __launch_bounds__(256) void qkv_h()
{
    extern __shared__ uint32_t smw[];
    const uint32_t sb = smem_u32(smw);

    const int tid  = threadIdx.x;
    const int lane = tid & 31, wid = tid >> 5;
    const int m0   = blockIdx.x * 128;
    const int g    = lane >> 2, tig = lane & 3;
    const int wm   = wid & 3,  wn  = wid >> 2;

    int rowA[2], cwA[2], rowB[3], cwB[3];
#pragma unroll
    for (int r = 0; r < 2; r++) { int idx = r*256+tid; rowA[r]=idx>>2; cwA[r]=(idx&3)<<2; }
#pragma unroll
    for (int r = 0; r < 3; r++) { int idx = r*256+tid; rowB[r]=idx>>2; cwB[r]=(idx&3)<<2; }

    const int a_lrow = wm * 32 + (lane & 15);
    const int a_kh   = ((lane >> 4) & 1) << 2;
    const int b_lrow = wn * 96 + ((lane >> 4) & 1) * 8 + (lane & 7);
    const int b_kh   = ((lane >> 3) & 1) << 2;

    float acc[2][12][4];
#pragma unroll
    for (int i = 0; i < 2; i++)
#pragma unroll
        for (int j = 0; j < 12; j++)
#pragma unroll
            for (int r = 0; r < 4; r++) acc[i][j][r] = 0.f;

#pragma unroll
    for (int r = 0; r < 2; r++)
        *(uint4*)&smw[W_A + rowA[r] * 20 + cwA[r]] =
            *(const uint4*)&g_xh[(size_t)(m0 + rowA[r]) * (Cc/2) + cwA[r]];
#pragma unroll
    for (int r = 0; r < 3; r++)
        *(uint4*)&smw[W_B + rowB[r] * 20 + cwB[r]] =
            *(const uint4*)&g_wth[(size_t)rowB[r] * (Cc/2) + cwB[r]];
    __syncthreads();

    for (int t = 0; t < NCH; t++) {
        const int buf = t & 1;
        uint4 stA[2], stB[3];
        if (t + 1 < NCH) {
            const int k0w = (t + 1) * (BKh / 2);
#pragma unroll
            for (int r = 0; r < 2; r++)
                stA[r] = *(const uint4*)&g_xh[(size_t)(m0 + rowA[r]) * (Cc/2) + k0w + cwA[r]];
#pragma unroll
            for (int r = 0; r < 3; r++)
                stB[r] = *(const uint4*)&g_wth[(size_t)rowB[r] * (Cc/2) + k0w + cwB[r]];
        }

        const uint32_t Abase = sb + (W_A + buf * 2560) * 4;
        const uint32_t Bbase = sb + (W_B + buf * 3840) * 4;

#pragma unroll
        for (int kk2 = 0; kk2 < 16; kk2 += 8) {
            uint32_t a[2][4];
#pragma unroll
            for (int i = 0; i < 2; i++)
                ldsm_x4(a[i][0], a[i][1], a[i][2], a[i][3],
                        Abase + (uint32_t)(((a_lrow + i * 16) * 20 + kk2 + a_kh) * 4));
            uint32_t bf[12][2];
#pragma unroll
            for (int p = 0; p < 6; p++) {
                uint32_t d0, d1, d2, d3;
                ldsm_x4(d0, d1, d2, d3,
                        Bbase + (uint32_t)(((b_lrow + p * 16) * 20 + kk2 + b_kh) * 4));
                bf[2*p][0] = d0; bf[2*p][1] = d1;
                bf[2*p+1][0] = d2; bf[2*p+1][1] = d3;
            }
#pragma unroll
            for (int j = 0; j < 12; j++) {
                mma_fp16(acc[0][j], a[0], bf[j][0], bf[j][1]);
                mma_fp16(acc[1][j], a[1], bf[j][0], bf[j][1]);
            }
        }

        if (t + 1 < NCH) {
            uint32_t* Ad = smw + W_A + (buf ^ 1) * 2560;
            uint32_t* Bd = smw + W_B + (buf ^ 1) * 3840;
#pragma unroll
            for (int r = 0; r < 2; r++)
                *(uint4*)&Ad[rowA[r] * 20 + cwA[r]] = stA[r];
#pragma unroll
            for (int r = 0; r < 3; r++)
                *(uint4*)&Bd[rowB[r] * 20 + cwB[r]] = stB[r];
        }
        __syncthreads();
    }

#pragma unroll
    for (int i = 0; i < 2; i++) {
        int r0 = m0 + wm * 32 + i * 16 + g;
#pragma unroll
        for (int j = 0; j < 12; j++) {
            int c = wn * 96 + j * 8 + tig * 2;
            uint32_t* op = (c < 64) ? g_qh : (c < 128 ? g_kh : g_vh);
            int oc = (c & 63) >> 1;
            op[(size_t)r0 * 32 + oc]       = h2pack(acc[i][j][0], acc[i][j][1]);
            op[(size_t)(r0 + 8) * 32 + oc] = h2pack(acc[i][j][2], acc[i][j][3]);
        }
    }
}

// ---------------------------------------------------------------------------
// Kernel 2: causal flash attention, split-KV x2, double-buffered K/V,
// forced occupancy 2 (launch_bounds) for latency hiding.
// ---------------------------------------------------------------------------
#define OQ  0
#define OKV 4608
#define ATTN_SMEM (13824 * 4)      // 55296 B (x2 CTAs = 110.6KB < 228KB)

__global__ __launch_bounds__(256, 2) void attn_mma(
    const float* __restrict__ amask)
{
    extern __shared__ uint32_t smw[];
    uint32_t* Qs = smw + OQ;
    const uint32_t sb = smem_u32(smw);

    const int b   = blockIdx.y;
    const int iq  = (int)gridDim.x - 1 - (int)blockIdx.x;   // long blocks first
    const int s   = blockIdx.z;
    const int q0  = iq * 128;
    const int tid = threadIdx.x;
    const int lane = tid & 31, w = tid >> 5;
    const int g = lane >> 2, t = lane & 3;

    const int ntiles = 2 * iq + 2;
    const int half   = ntiles >> 1;
    const int tstart = s * half;
    const int tend   = tstart + half;

    // stage Q
    const uint32_t* qp = g_qh + ((size_t)b * Tt + q0) * 32;
#pragma unroll
    for (int r = 0; r < 4; r++) {
        int idx = r * 256 + tid;
        int row = idx >> 3, cw = (idx & 7) << 2;
        *(uint4*)&Qs[row * 36 + cw] = *(const uint4*)&qp[row * 32 + cw];
    }

    float m0 = -INFINITY, m1 = -INFINITY, l0 = 0.f, l1 = 0.f;
    float o[8][4];
#pragma unroll
    for (int f = 0; f < 8; f++)
#pragma unroll
        for (int r = 0; r < 4; r++) o[f][r] = 0.f;

    const float am0 = amask[(size_t)b * Tt + q0 + w * 16 + g];
    const float am1 = amask[(size_t)b * Tt + q0 + w * 16 + g + 8];
    const int qg0 = q0 + w * 16 + g;
    const int qg1 = qg0 + 8;

    int srow[2], scw[2];
#pragma unroll
    for (int r = 0; r < 2; r++) { int idx = r*256+tid; srow[r]=idx>>3; scw[r]=(idx&7)<<2; }

    // prologue: stage tile tstart into buffer 0
    {
        const uint32_t* kp = g_kh + ((size_t)b * Tt + tstart * 64) * 32;
        const uint32_t* vp = g_vh + ((size_t)b * Tt + tstart * 64) * 32;
        uint32_t* Kd = smw + OKV;
        uint32_t* Vd = smw + OKV + 2304;
#pragma unroll
        for (int r = 0; r < 2; r++) {
            *(uint4*)&Kd[srow[r] * 36 + scw[r]] = *(const uint4*)&kp[srow[r] * 32 + scw[r]];
            *(uint4*)&Vd[srow[r] * 36 + scw[r]] = *(const uint4*)&vp[srow[r] * 32 + scw[r]];
        }
    }
    __syncthreads();

    for (int tt = tstart; tt < tend; tt++) {
        const int cur = (tt - tstart) & 1;
        const int j0 = tt * 64;
        const bool more = (tt + 1 < tend);

        uint4 stK[2], stV[2];
        if (more) {
            const uint32_t* kp = g_kh + ((size_t)b * Tt + (tt + 1) * 64) * 32;
            const uint32_t* vp = g_vh + ((size_t)b * Tt + (tt + 1) * 64) * 32;
#pragma unroll
            for (int r = 0; r < 2; r++) {
                stK[r] = *(const uint4*)&kp[srow[r] * 32 + scw[r]];
                stV[r] = *(const uint4*)&vp[srow[r] * 32 + scw[r]];
            }
        }

        const uint32_t* Ks = smw + OKV + cur * 4608;
        const uint32_t sbv = sb + (uint32_t)((OKV + cur * 4608 + 2304) * 4);

        // S = Q K^T
        float c[8][4];
#pragma unroll
        for (int f = 0; f < 8; f++)
#pragma unroll
            for (int r = 0; r < 4; r++) c[f][r] = 0.f;
#pragma unroll
        for (int ks = 0; ks < 4; ks++) {
            uint32_t a[4];
            int base = (w * 16 + g) * 36 + ks * 8 + t;
            a[0] = Qs[base];
            a[1] = Qs[base + 8 * 36];
            a[2] = Qs[base + 4];
            a[3] = Qs[base + 8 * 36 + 4];
#pragma unroll
            for (int f = 0; f < 8; f++) {
                int nb = (f * 8 + g) * 36 + ks * 8 + t;
                mma_fp16(c[f], a, Ks[nb], Ks[nb + 4]);
            }
        }

        // masks
        float mx0 = -INFINITY, mx1 = -INFINITY;
#pragma unroll
        for (int f = 0; f < 8; f++) {
            int col = j0 + f * 8 + t * 2;
            float v0 = c[f][0] * 0.125f * am0;
            float v1 = c[f][1] * 0.125f * am0;
            float v2 = c[f][2] * 0.125f * am1;
            float v3 = c[f][3] * 0.125f * am1;
            if (v0 == 0.f || col     > qg0) v0 = -INFINITY;
            if (v1 == 0.f || col + 1 > qg0) v1 = -INFINITY;
            if (v2 == 0.f || col     > qg1) v2 = -INFINITY;
            if (v3 == 0.f || col + 1 > qg1) v3 = -INFINITY;
            c[f][0] = v0; c[f][1] = v1; c[f][2] = v2; c[f][3] = v3;
            mx0 = fmaxf(mx0, fmaxf(v0, v1));
            mx1 = fmaxf(mx1, fmaxf(v2, v3));
        }
        mx0 = fmaxf(mx0, __shfl_xor_sync(0xffffffffu, mx0, 1));
        mx0 = fmaxf(mx0, __shfl_xor_sync(0xffffffffu, mx0, 2));
        mx1 = fmaxf(mx1, __shfl_xor_sync(0xffffffffu, mx1, 1));
        mx1 = fmaxf(mx1, __shfl_xor_sync(0xffffffffu, mx1, 2));

        float mn0 = fmaxf(m0, mx0), mn1 = fmaxf(m1, mx1);
        float alpha0, alpha1, ls0 = 0.f, ls1 = 0.f;
        uint32_t p01[8], p23[8];
        if (mn0 == -INFINITY) {
            alpha0 = 1.f;
#pragma unroll
            for (int f = 0; f < 8; f++) { c[f][0] = 0.f; c[f][1] = 0.f; }
        } else {
            alpha0 = __expf(m0 - mn0);
#pragma unroll
            for (int f = 0; f < 8; f++) {
                c[f][0] = __expf(c[f][0] - mn0);
                c[f][1] = __expf(c[f][1] - mn0);
                ls0 += c[f][0] + c[f][1];
            }
        }
        if (mn1 == -INFINITY) {
            alpha1 = 1.f;
#pragma unroll
            for (int f = 0; f < 8; f++) { c[f][2] = 0.f; c[f][3] = 0.f; }
        } else {
            alpha1 = __expf(m1 - mn1);
#pragma unroll
            for (int f = 0; f < 8; f++) {
                c[f][2] = __expf(c[f][2] - mn1);
                c[f][3] = __expf(c[f][3] - mn1);
                ls1 += c[f][2] + c[f][3];
            }
        }
        m0 = mn0; m1 = mn1;
        ls0 += __shfl_xor_sync(0xffffffffu, ls0, 1);
        ls0 += __shfl_xor_sync(0xffffffffu, ls0, 2);
        ls1 += __shfl_xor_sync(0xffffffffu, ls1, 1);
        ls1 += __shfl_xor_sync(0xffffffffu, ls1, 2);
        l0 = l0 * alpha0 + ls0;
        l1 = l1 * alpha1 + ls1;

#pragma unroll
        for (int f = 0; f < 8; f++) {
            p01[f] = h2pack(c[f][0], c[f][1]);
            p23[f] = h2pack(c[f][2], c[f][3]);
            o[f][0] *= alpha0; o[f][1] *= alpha0;
            o[f][2] *= alpha1; o[f][3] *= alpha1;
        }

        // O += P V
        const int vrow = (lane & 15);
        const int vcb  = ((lane >> 4) & 1) << 2;
#pragma unroll
        for (int ss = 0; ss < 4; ss++) {
            uint32_t a[4];
            a[0] = p01[2 * ss];     a[1] = p23[2 * ss];
            a[2] = p01[2 * ss + 1]; a[3] = p23[2 * ss + 1];
#pragma unroll
            for (int p = 0; p < 4; p++) {
                uint32_t d0, d1, d2, d3;
                ldsm_x4_t(d0, d1, d2, d3,
                          sbv + (uint32_t)((((ss * 16 + vrow) * 36) + p * 8 + vcb) * 4));
                mma_fp16(o[2 * p],     a, d0, d1);
                mma_fp16(o[2 * p + 1], a, d2, d3);
            }
        }

        if (more) {
            uint32_t* Kd = smw + OKV + (cur ^ 1) * 4608;
            uint32_t* Vd = Kd + 2304;
#pragma unroll
            for (int r = 0; r < 2; r++) {
                *(uint4*)&Kd[srow[r] * 36 + scw[r]] = stK[r];
                *(uint4*)&Vd[srow[r] * 36 + scw[r]] = stV[r];
            }
        }
        __syncthreads();
    }

    // epilogue: write unnormalized partials
    float* po0 = g_po + ((size_t)s * M_TOT + (size_t)b * Tt + qg0) * 64;
    float* po1 = g_po + ((size_t)s * M_TOT + (size_t)b * Tt + qg1) * 64;
#pragma unroll
    for (int f = 0; f < 8; f++) {
        int col = f * 8 + t * 2;
        *(float2*)(po0 + col) = make_float2(o[f][0], o[f][1]);
        *(float2*)(po1 + col) = make_float2(o[f][2], o[f][3]);
    }
    if (t == 0) {
        size_t r0 = (size_t)s * M_TOT + (size_t)b * Tt + qg0;
        size_t r1 = (size_t)s * M_TOT + (size_t)b * Tt + qg1;
        g_pm[r0] = m0; g_pl[r0] = l0;
        g_pm[r1] = m1; g_pl[r1] = l1;
    }
}

// ---------------------------------------------------------------------------
// Kernel 3: combine two splits
// ---------------------------------------------------------------------------
__global__ void combine(float* __restrict__ out)
{
    int idx = blockIdx.x * 256 + threadIdx.x;
    int row = idx >> 4;
    int c4  = (idx & 15) << 2;
    float m0 = g_pm[row], m1 = g_pm[M_TOT + row];
    float l0 = g_pl[row], l1 = g_pl[M_TOT + row];
    float M = fmaxf(m0, m1);
    float w0 = (m0 == -INFINITY) ? 0.f : __expf(m0 - M);
    float w1 = (m1 == -INFINITY) ? 0.f : __expf(m1 - M);
    float l = l0 * w0 + l1 * w1;
    float inv = (l > 0.f) ? (1.f / l) : 0.f;
    float4 a  = *(const float4*)&g_po[(size_t)row * 64 + c4];
    float4 bb = *(const float4*)&g_po[(size_t)(M_TOT + row) * 64 + c4];
    float4 r;
    r.x = (a.x * w0 + bb.x * w1) * inv;
    r.y = (a.y * w0 + bb.y * w1) * inv;
    r.z = (a.z * w0 + bb.z * w1) * inv;
    r.w = (a.w * w0 + bb.w * w1) * inv;
    *(float4*)&out[(size_t)row * 64 + c4] = r;
}

// ---------------------------------------------------------------------------
extern "C" void kernel_launch(void* const* d_in, const int* in_sizes, int n_in,
                              void* d_out, int out_size)
{
    const float* x  = (const float*)d_in[0];
    const float* am = (const float*)d_in[1];
    const float* Wq = (const float*)d_in[2];
    const float* Wk = (const float*)d_in[3];
    const float* Wv = (const float*)d_in[4];
    float*       out = (float*)d_out;

    wtrans<<<36, 256>>>(Wq, Wk, Wv);
    xcvt<<<(M_TOT * Cc / 8) / 256, 256>>>(x);

    cudaFuncSetAttribute(qkv_h,
                         cudaFuncAttributeMaxDynamicSharedMemorySize, QKV_SMEM);
    qkv_h<<<M_TOT / 128, 256, QKV_SMEM>>>();

    cudaFuncSetAttribute(attn_mma,
                         cudaFuncAttributeMaxDynamicSharedMemorySize, ATTN_SMEM);
    dim3 g2(Tt / 128, Bb, 2);
    attn_mma<<<g2, 256, ATTN_SMEM>>>(am);

    combine<<<(M_TOT * 16) / 256, 256>>>(out);
}

// round 12
// speedup vs baseline: 5.9711x; 1.1978x over previous
#include <cuda_runtime.h>
#include <cuda_fp16.h>
#include <math.h>
#include <stdint.h>

#define Bb 8
#define Tt 2048
#define Cc 768
#define Hh 64
#define M_TOT (Bb*Tt)

// fp16 scratch (half2 packed in uint32)
__device__ uint32_t g_xh[M_TOT*Cc/2];    // x as fp16 [row][k]
__device__ uint32_t g_wth[192*Cc/2];     // fused transposed weights fp16 [n][k]
__device__ uint32_t g_qh[M_TOT*32];      // q fp16 [row][h]
__device__ uint32_t g_kh[M_TOT*32];
__device__ uint32_t g_vh[M_TOT*32];
// split-KV partials (up to 4 splits)
__device__ float g_po[4 * M_TOT * 64];   // unnormalized O per split
__device__ float g_pm[4 * M_TOT];
__device__ float g_pl[4 * M_TOT];

// ---------------------------------------------------------------------------
// helpers
// ---------------------------------------------------------------------------
__device__ __forceinline__ void mma_fp16(float* d, const uint32_t* a,
                                         uint32_t b0, uint32_t b1) {
    asm volatile(
        "mma.sync.aligned.m16n8k16.row.col.f32.f16.f16.f32 "
        "{%0,%1,%2,%3}, {%4,%5,%6,%7}, {%8,%9}, {%0,%1,%2,%3};"
        : "+f"(d[0]), "+f"(d[1]), "+f"(d[2]), "+f"(d[3])
        : "r"(a[0]), "r"(a[1]), "r"(a[2]), "r"(a[3]), "r"(b0), "r"(b1));
}

__device__ __forceinline__ void ldsm_x4(uint32_t& d0, uint32_t& d1,
                                        uint32_t& d2, uint32_t& d3,
                                        uint32_t saddr) {
    asm volatile("ldmatrix.sync.aligned.m8n8.x4.shared.b16 {%0,%1,%2,%3}, [%4];"
                 : "=r"(d0), "=r"(d1), "=r"(d2), "=r"(d3) : "r"(saddr));
}

__device__ __forceinline__ void ldsm_x4_t(uint32_t& d0, uint32_t& d1,
                                          uint32_t& d2, uint32_t& d3,
                                          uint32_t saddr) {
    asm volatile("ldmatrix.sync.aligned.m8n8.x4.trans.shared.b16 {%0,%1,%2,%3}, [%4];"
                 : "=r"(d0), "=r"(d1), "=r"(d2), "=r"(d3) : "r"(saddr));
}

__device__ __forceinline__ uint32_t smem_u32(const void* p) {
    uint32_t a;
    asm("{ .reg .u64 t; cvta.to.shared.u64 t, %1; cvt.u32.u64 %0, t; }"
        : "=r"(a) : "l"(p));
    return a;
}

__device__ __forceinline__ uint32_t h2pack(float x, float y) {
    __half2 h = __floats2half2_rn(x, y);
    return *(uint32_t*)&h;
}

// ---------------------------------------------------------------------------
// Kernel 0a: transpose+fuse weights -> fp16 g_wth[n][k] (coalesced)
// ---------------------------------------------------------------------------
__global__ void wtrans(const float* __restrict__ Wq,
                       const float* __restrict__ Wk,
                       const float* __restrict__ Wv)
{
    __shared__ float s[64][65];
    const int wsel = blockIdx.x / 12;
    const int k0   = (blockIdx.x % 12) * 64;
    const float* W = (wsel == 0) ? Wq : (wsel == 1 ? Wk : Wv);
    const int tid = threadIdx.x;

#pragma unroll
    for (int r = 0; r < 16; r++) {
        int idx = r * 256 + tid;
        int k = idx >> 6, h = idx & 63;
        s[k][h] = W[(size_t)(k0 + k) * Hh + h];
    }
    __syncthreads();

#pragma unroll
    for (int r = 0; r < 8; r++) {
        int idx = r * 256 + tid;
        int h = idx >> 5, kw = idx & 31;
        g_wth[(size_t)(wsel * 64 + h) * (Cc / 2) + (k0 >> 1) + kw] =
            h2pack(s[2 * kw][h], s[2 * kw + 1][h]);
    }
}

// ---------------------------------------------------------------------------
// Kernel 0b: x -> fp16 g_xh
// ---------------------------------------------------------------------------
__global__ void xcvt(const float* __restrict__ x)
{
    int t = blockIdx.x * 256 + threadIdx.x;
    const float4* xp = (const float4*)x;
    float4 a = xp[2 * t], b = xp[2 * t + 1];
    uint4 o;
    o.x = h2pack(a.x, a.y); o.y = h2pack(a.z, a.w);
    o.z = h2pack(b.x, b.y); o.w = h2pack(b.z, b.w);
    *(uint4*)&g_xh[4 * t] = o;
}

// ---------------------------------------------------------------------------
// Kernel 1: QKV projection (unchanged).
// ---------------------------------------------------------------------------
#define BKh 32
#define NCH (Cc / BKh)
#define W_A 0
#define W_B 5120
#define QKV_SMEM (12800 * 4)

__global__ __launch_bounds__(256) void qkv_h()
{
    extern __shared__ uint32_t smw[];
    const uint32_t sb = smem_u32(smw);

    const int tid  = threadIdx.x;
    const int lane = tid & 31, wid = tid >> 5;
    const int m0   = blockIdx.x * 128;
    const int g    = lane >> 2, tig = lane & 3;
    const int wm   = wid & 3,  wn  = wid >> 2;

    int rowA[2], cwA[2], rowB[3], cwB[3];
#pragma unroll
    for (int r = 0; r < 2; r++) { int idx = r*256+tid; rowA[r]=idx>>2; cwA[r]=(idx&3)<<2; }
#pragma unroll
    for (int r = 0; r < 3; r++) { int idx = r*256+tid; rowB[r]=idx>>2; cwB[r]=(idx&3)<<2; }

    const int a_lrow = wm * 32 + (lane & 15);
    const int a_kh   = ((lane >> 4) & 1) << 2;
    const int b_lrow = wn * 96 + ((lane >> 4) & 1) * 8 + (lane & 7);
    const int b_kh   = ((lane >> 3) & 1) << 2;

    float acc[2][12][4];
#pragma unroll
    for (int i = 0; i < 2; i++)
#pragma unroll
        for (int j = 0; j < 12; j++)
#pragma unroll
            for (int r = 0; r < 4; r++) acc[i][j][r] = 0.f;

#pragma unroll
    for (int r = 0; r < 2; r++)
        *(uint4*)&smw[W_A + rowA[r] * 20 + cwA[r]] =
            *(const uint4*)&g_xh[(size_t)(m0 + rowA[r]) * (Cc/2) + cwA[r]];
#pragma unroll
    for (int r = 0; r < 3; r++)
        *(uint4*)&smw[W_B + rowB[r] * 20 + cwB[r]] =
            *(const uint4*)&g_wth[(size_t)rowB[r] * (Cc/2) + cwB[r]];
    __syncthreads();

    for (int t = 0; t < NCH; t++) {
        const int buf = t & 1;
        uint4 stA[2], stB[3];
        if (t + 1 < NCH) {
            const int k0w = (t + 1) * (BKh / 2);
#pragma unroll
            for (int r = 0; r < 2; r++)
                stA[r] = *(const uint4*)&g_xh[(size_t)(m0 + rowA[r]) * (Cc/2) + k0w + cwA[r]];
#pragma unroll
            for (int r = 0; r < 3; r++)
                stB[r] = *(const uint4*)&g_wth[(size_t)rowB[r] * (Cc/2) + k0w + cwB[r]];
        }

        const uint32_t Abase = sb + (W_A + buf * 2560) * 4;
        const uint32_t Bbase = sb + (W_B + buf * 3840) * 4;

#pragma unroll
        for (int kk2 = 0; kk2 < 16; kk2 += 8) {
            uint32_t a[2][4];
#pragma unroll
            for (int i = 0; i < 2; i++)
                ldsm_x4(a[i][0], a[i][1], a[i][2], a[i][3],
                        Abase + (uint32_t)(((a_lrow + i * 16) * 20 + kk2 + a_kh) * 4));
            uint32_t bf[12][2];
#pragma unroll
            for (int p = 0; p < 6; p++) {
                uint32_t d0, d1, d2, d3;
                ldsm_x4(d0, d1, d2, d3,
                        Bbase + (uint32_t)(((b_lrow + p * 16) * 20 + kk2 + b_kh) * 4));
                bf[2*p][0] = d0; bf[2*p][1] = d1;
                bf[2*p+1][0] = d2; bf[2*p+1][1] = d3;
            }
#pragma unroll
            for (int j = 0; j < 12; j++) {
                mma_fp16(acc[0][j], a[0], bf[j][0], bf[j][1]);
                mma_fp16(acc[1][j], a[1], bf[j][0], bf[j][1]);
            }
        }

        if (t + 1 < NCH) {
            uint32_t* Ad = smw + W_A + (buf ^ 1) * 2560;
            uint32_t* Bd = smw + W_B + (buf ^ 1) * 3840;
#pragma unroll
            for (int r = 0; r < 2; r++)
                *(uint4*)&Ad[rowA[r] * 20 + cwA[r]] = stA[r];
#pragma unroll
            for (int r = 0; r < 3; r++)
                *(uint4*)&Bd[rowB[r] * 20 + cwB[r]] = stB[r];
        }
        __syncthreads();
    }

#pragma unroll
    for (int i = 0; i < 2; i++) {
        int r0 = m0 + wm * 32 + i * 16 + g;
#pragma unroll
        for (int j = 0; j < 12; j++) {
            int c = wn * 96 + j * 8 + tig * 2;
            uint32_t* op = (c < 64) ? g_qh : (c < 128 ? g_kh : g_vh);
            int oc = (c & 63) >> 1;
            op[(size_t)r0 * 32 + oc]       = h2pack(acc[i][j][0], acc[i][j][1]);
            op[(size_t)(r0 + 8) * 32 + oc] = h2pack(acc[i][j][2], acc[i][j][3]);
        }
    }
}

// ---------------------------------------------------------------------------
// Kernel 2: causal flash attention, ADAPTIVE split-KV (units <= 8 k-tiles).
// grid = (40, 8): x enumerates (iq, part) units longest-first, y = batch.
//   x in [0,16):  iq = 15 - x/4,        part = x%4, nsplit = 4
//   x in [16,28): iq = 11 - (x-16)/3,   part = %3,  nsplit = 3
//   x in [28,36): iq = 7  - (x-28)/2,   part = %2,  nsplit = 2
//   x in [36,40): iq = 3  - (x-36),     part = 0,   nsplit = 1
// ---------------------------------------------------------------------------
#define OQ  0
#define OKV 4608
#define ATTN_SMEM (13824 * 4)

__global__ __launch_bounds__(256, 2) void attn_mma(
    const float* __restrict__ amask)
{
    extern __shared__ uint32_t smw[];
    uint32_t* Qs = smw + OQ;
    const uint32_t sb = smem_u32(smw);

    const int b   = blockIdx.y;
    const int x   = blockIdx.x;
    int iq, part, ns;
    if (x < 16)      { iq = 15 - (x >> 2);      part = x & 3;        ns = 4; }
    else if (x < 28) { iq = 11 - (x - 16) / 3;  part = (x - 16) % 3; ns = 3; }
    else if (x < 36) { iq = 7  - ((x - 28) >> 1); part = (x - 28) & 1; ns = 2; }
    else             { iq = 3  - (x - 36);      part = 0;            ns = 1; }

    const int q0  = iq * 128;
    const int ntiles = 2 * iq + 2;
    const int base = ntiles / ns, rem = ntiles % ns;
    const int tstart = part * base + min(part, rem);
    const int tend   = tstart + base + (part < rem ? 1 : 0);

    const int tid = threadIdx.x;
    const int lane = tid & 31, w = tid >> 5;
    const int g = lane >> 2, t = lane & 3;

    // stage Q
    const uint32_t* qp = g_qh + ((size_t)b * Tt + q0) * 32;
#pragma unroll
    for (int r = 0; r < 4; r++) {
        int idx = r * 256 + tid;
        int row = idx >> 3, cw = (idx & 7) << 2;
        *(uint4*)&Qs[row * 36 + cw] = *(const uint4*)&qp[row * 32 + cw];
    }

    float m0 = -INFINITY, m1 = -INFINITY, l0 = 0.f, l1 = 0.f;
    float o[8][4];
#pragma unroll
    for (int f = 0; f < 8; f++)
#pragma unroll
        for (int r = 0; r < 4; r++) o[f][r] = 0.f;

    const float am0 = amask[(size_t)b * Tt + q0 + w * 16 + g];
    const float am1 = amask[(size_t)b * Tt + q0 + w * 16 + g + 8];
    const int qg0 = q0 + w * 16 + g;
    const int qg1 = qg0 + 8;

    int srow[2], scw[2];
#pragma unroll
    for (int r = 0; r < 2; r++) { int idx = r*256+tid; srow[r]=idx>>3; scw[r]=(idx&7)<<2; }

    // prologue: stage tile tstart into buffer 0
    {
        const uint32_t* kp = g_kh + ((size_t)b * Tt + tstart * 64) * 32;
        const uint32_t* vp = g_vh + ((size_t)b * Tt + tstart * 64) * 32;
        uint32_t* Kd = smw + OKV;
        uint32_t* Vd = smw + OKV + 2304;
#pragma unroll
        for (int r = 0; r < 2; r++) {
            *(uint4*)&Kd[srow[r] * 36 + scw[r]] = *(const uint4*)&kp[srow[r] * 32 + scw[r]];
            *(uint4*)&Vd[srow[r] * 36 + scw[r]] = *(const uint4*)&vp[srow[r] * 32 + scw[r]];
        }
    }
    __syncthreads();

    for (int tt = tstart; tt < tend; tt++) {
        const int cur = (tt - tstart) & 1;
        const int j0 = tt * 64;
        const bool more = (tt + 1 < tend);

        uint4 stK[2], stV[2];
        if (more) {
            const uint32_t* kp = g_kh + ((size_t)b * Tt + (tt + 1) * 64) * 32;
            const uint32_t* vp = g_vh + ((size_t)b * Tt + (tt + 1) * 64) * 32;
#pragma unroll
            for (int r = 0; r < 2; r++) {
                stK[r] = *(const uint4*)&kp[srow[r] * 32 + scw[r]];
                stV[r] = *(const uint4*)&vp[srow[r] * 32 + scw[r]];
            }
        }

        const uint32_t* Ks = smw + OKV + cur * 4608;
        const uint32_t sbv = sb + (uint32_t)((OKV + cur * 4608 + 2304) * 4);

        // S = Q K^T
        float c[8][4];
#pragma unroll
        for (int f = 0; f < 8; f++)
#pragma unroll
            for (int r = 0; r < 4; r++) c[f][r] = 0.f;
#pragma unroll
        for (int ks = 0; ks < 4; ks++) {
            uint32_t a[4];
            int baseq = (w * 16 + g) * 36 + ks * 8 + t;
            a[0] = Qs[baseq];
            a[1] = Qs[baseq + 8 * 36];
            a[2] = Qs[baseq + 4];
            a[3] = Qs[baseq + 8 * 36 + 4];
#pragma unroll
            for (int f = 0; f < 8; f++) {
                int nb = (f * 8 + g) * 36 + ks * 8 + t;
                mma_fp16(c[f], a, Ks[nb], Ks[nb + 4]);
            }
        }

        // masks
        float mx0 = -INFINITY, mx1 = -INFINITY;
#pragma unroll
        for (int f = 0; f < 8; f++) {
            int col = j0 + f * 8 + t * 2;
            float v0 = c[f][0] * 0.125f * am0;
            float v1 = c[f][1] * 0.125f * am0;
            float v2 = c[f][2] * 0.125f * am1;
            float v3 = c[f][3] * 0.125f * am1;
            if (v0 == 0.f || col     > qg0) v0 = -INFINITY;
            if (v1 == 0.f || col + 1 > qg0) v1 = -INFINITY;
            if (v2 == 0.f || col     > qg1) v2 = -INFINITY;
            if (v3 == 0.f || col + 1 > qg1) v3 = -INFINITY;
            c[f][0] = v0; c[f][1] = v1; c[f][2] = v2; c[f][3] = v3;
            mx0 = fmaxf(mx0, fmaxf(v0, v1));
            mx1 = fmaxf(mx1, fmaxf(v2, v3));
        }
        mx0 = fmaxf(mx0, __shfl_xor_sync(0xffffffffu, mx0, 1));
        mx0 = fmaxf(mx0, __shfl_xor_sync(0xffffffffu, mx0, 2));
        mx1 = fmaxf(mx1, __shfl_xor_sync(0xffffffffu, mx1, 1));
        mx1 = fmaxf(mx1, __shfl_xor_sync(0xffffffffu, mx1, 2));

        float mn0 = fmaxf(m0, mx0), mn1 = fmaxf(m1, mx1);
        float alpha0, alpha1, ls0 = 0.f, ls1 = 0.f;
        uint32_t p01[8], p23[8];
        if (mn0 == -INFINITY) {
            alpha0 = 1.f;
#pragma unroll
            for (int f = 0; f < 8; f++) { c[f][0] = 0.f; c[f][1] = 0.f; }
        } else {
            alpha0 = __expf(m0 - mn0);
#pragma unroll
            for (int f = 0; f < 8; f++) {
                c[f][0] = __expf(c[f][0] - mn0);
                c[f][1] = __expf(c[f][1] - mn0);
                ls0 += c[f][0] + c[f][1];
            }
        }
        if (mn1 == -INFINITY) {
            alpha1 = 1.f;
#pragma unroll
            for (int f = 0; f < 8; f++) { c[f][2] = 0.f; c[f][3] = 0.f; }
        } else {
            alpha1 = __expf(m1 - mn1);
#pragma unroll
            for (int f = 0; f < 8; f++) {
                c[f][2] = __expf(c[f][2] - mn1);
                c[f][3] = __expf(c[f][3] - mn1);
                ls1 += c[f][2] + c[f][3];
            }
        }
        m0 = mn0; m1 = mn1;
        ls0 += __shfl_xor_sync(0xffffffffu, ls0, 1);
        ls0 += __shfl_xor_sync(0xffffffffu, ls0, 2);
        ls1 += __shfl_xor_sync(0xffffffffu, ls1, 1);
        ls1 += __shfl_xor_sync(0xffffffffu, ls1, 2);
        l0 = l0 * alpha0 + ls0;
        l1 = l1 * alpha1 + ls1;

#pragma unroll
        for (int f = 0; f < 8; f++) {
            p01[f] = h2pack(c[f][0], c[f][1]);
            p23[f] = h2pack(c[f][2], c[f][3]);
            o[f][0] *= alpha0; o[f][1] *= alpha0;
            o[f][2] *= alpha1; o[f][3] *= alpha1;
        }

        // O += P V
        const int vrow = (lane & 15);
        const int vcb  = ((lane >> 4) & 1) << 2;
#pragma unroll
        for (int ss = 0; ss < 4; ss++) {
            uint32_t a[4];
            a[0] = p01[2 * ss];     a[1] = p23[2 * ss];
            a[2] = p01[2 * ss + 1]; a[3] = p23[2 * ss + 1];
#pragma unroll
            for (int p = 0; p < 4; p++) {
                uint32_t d0, d1, d2, d3;
                ldsm_x4_t(d0, d1, d2, d3,
                          sbv + (uint32_t)((((ss * 16 + vrow) * 36) + p * 8 + vcb) * 4));
                mma_fp16(o[2 * p],     a, d0, d1);
                mma_fp16(o[2 * p + 1], a, d2, d3);
            }
        }

        if (more) {
            uint32_t* Kd = smw + OKV + (cur ^ 1) * 4608;
            uint32_t* Vd = Kd + 2304;
#pragma unroll
            for (int r = 0; r < 2; r++) {
                *(uint4*)&Kd[srow[r] * 36 + scw[r]] = stK[r];
                *(uint4*)&Vd[srow[r] * 36 + scw[r]] = stV[r];
            }
        }
        __syncthreads();
    }

    // epilogue: write unnormalized partials into slot `part`
    float* po0 = g_po + ((size_t)part * M_TOT + (size_t)b * Tt + qg0) * 64;
    float* po1 = g_po + ((size_t)part * M_TOT + (size_t)b * Tt + qg1) * 64;
#pragma unroll
    for (int f = 0; f < 8; f++) {
        int col = f * 8 + t * 2;
        *(float2*)(po0 + col) = make_float2(o[f][0], o[f][1]);
        *(float2*)(po1 + col) = make_float2(o[f][2], o[f][3]);
    }
    if (t == 0) {
        size_t r0 = (size_t)part * M_TOT + (size_t)b * Tt + qg0;
        size_t r1 = (size_t)part * M_TOT + (size_t)b * Tt + qg1;
        g_pm[r0] = m0; g_pl[r0] = l0;
        g_pm[r1] = m1; g_pl[r1] = l1;
    }
}

// ---------------------------------------------------------------------------
// Kernel 3: combine up to 4 splits (nsplit derived from row's q-block)
// ---------------------------------------------------------------------------
__global__ void combine(float* __restrict__ out)
{
    int idx = blockIdx.x * 256 + threadIdx.x;
    int row = idx >> 4;
    int c4  = (idx & 15) << 2;
    int iq  = (row & (Tt - 1)) >> 7;
    int ns  = (iq >= 12) ? 4 : (iq >= 8) ? 3 : (iq >= 4) ? 2 : 1;

    float mv[4], lv[4];
    float M = -INFINITY;
    for (int s = 0; s < ns; s++) {
        mv[s] = g_pm[(size_t)s * M_TOT + row];
        lv[s] = g_pl[(size_t)s * M_TOT + row];
        M = fmaxf(M, mv[s]);
    }
    float l = 0.f;
    float wv[4];
    for (int s = 0; s < ns; s++) {
        wv[s] = (mv[s] == -INFINITY) ? 0.f : __expf(mv[s] - M);
        l += lv[s] * wv[s];
    }
    float inv = (l > 0.f) ? (1.f / l) : 0.f;

    float4 acc = make_float4(0.f, 0.f, 0.f, 0.f);
    for (int s = 0; s < ns; s++) {
        float4 a = *(const float4*)&g_po[((size_t)s * M_TOT + row) * 64 + c4];
        acc.x += a.x * wv[s]; acc.y += a.y * wv[s];
        acc.z += a.z * wv[s]; acc.w += a.w * wv[s];
    }
    acc.x *= inv; acc.y *= inv; acc.z *= inv; acc.w *= inv;
    *(float4*)&out[(size_t)row * 64 + c4] = acc;
}

// ---------------------------------------------------------------------------
extern "C" void kernel_launch(void* const* d_in, const int* in_sizes, int n_in,
                              void* d_out, int out_size)
{
    const float* x  = (const float*)d_in[0];
    const float* am = (const float*)d_in[1];
    const float* Wq = (const float*)d_in[2];
    const float* Wk = (const float*)d_in[3];
    const float* Wv = (const float*)d_in[4];
    float*       out = (float*)d_out;

    wtrans<<<36, 256>>>(Wq, Wk, Wv);
    xcvt<<<(M_TOT * Cc / 8) / 256, 256>>>(x);

    cudaFuncSetAttribute(qkv_h,
                         cudaFuncAttributeMaxDynamicSharedMemorySize, QKV_SMEM);
    qkv_h<<<M_TOT / 128, 256, QKV_SMEM>>>();

    cudaFuncSetAttribute(attn_mma,
                         cudaFuncAttributeMaxDynamicSharedMemorySize, ATTN_SMEM);
    dim3 g2(40, Bb);
    attn_mma<<<g2, 256, ATTN_SMEM>>>(am);

    combine<<<(M_TOT * 16) / 256, 256>>>(out);
}